// round 1
// baseline (speedup 1.0000x reference)
#include <cuda_runtime.h>
#include <cuda_bf16.h>
#include <math.h>

#define B_ 2
#define T_ 1024
#define C_ 256
#define F_ 1024
#define E_ 32
#define V_ 50257
#define H_ 8
#define D_ 32
#define N_ 2048

// ---------------- scratch (static device globals; no allocations) ----------------
__device__ float g_hs[N_ * C_];                     // residual stream
__device__ float g_ln[N_ * C_];                     // LN output (reused for ln1 and ln2)
__device__ float g_q[N_ * C_];
__device__ float g_k[N_ * C_];
__device__ float g_v[N_ * C_];
__device__ float g_ao[N_ * C_];
__device__ float g_attn[(size_t)B_ * H_ * T_ * T_]; // 64 MB attention matrix
__device__ float g_Hbuf[67108864];                  // E*N*F = 32*2048*1024 (256 MB)
__device__ float g_rw[N_ * E_];
__device__ float g_snorm[E_];

__device__ __forceinline__ float gelu_f(float x) {
    return 0.5f * x * (1.0f + erff(x * 0.70710678118654752440f));
}

// ---------------- tiled SGEMM: 128x128 block, BK=8, 8x8 per thread ----------------
// A: [M,K] row-major (lda=K), B: [K,N] row-major (ldb=N).
// MODE 0: C = acc            (plain, e.g. qkv / lm_head)
// MODE 1: C = gelu(acc)      (MoE up-proj; z = expert)
// MODE 2: feo = mask[row,z]*acc, layout [row, E, C]  (MoE down-proj; z = expert)
// MODE 4: C += acc           (residual accumulate)
template <int MODE>
__global__ __launch_bounds__(256) void sgemm128(
    const float* __restrict__ A, const float* __restrict__ B, float* __restrict__ Cmat,
    int M, int N, int K, long sA, long sB, long sC,
    const float* __restrict__ mask, int moeE, int moeC)
{
    const int BM = 128, BN = 128, BK = 8;
    int z = blockIdx.z;
    A += (long)z * sA;
    B += (long)z * sB;

    __shared__ float As[BK][BM];
    __shared__ float Bs[BK][BN + 4];

    int tid = threadIdx.x;
    int rowBase = blockIdx.y * BM;
    int colBase = blockIdx.x * BN;
    int tr = tid / 16;        // 0..15
    int tc = tid % 16;        // 0..15

    float acc[8][8];
#pragma unroll
    for (int i = 0; i < 8; i++)
#pragma unroll
        for (int j = 0; j < 8; j++) acc[i][j] = 0.0f;

    int am = tid >> 1;         // 0..127
    int ak = (tid & 1) * 4;    // 0 or 4

    for (int k0 = 0; k0 < K; k0 += BK) {
        // A tile (float4, K always multiple of 8 and 16B-aligned rows)
        float4 av = *(const float4*)(A + (long)(rowBase + am) * K + k0 + ak);
        As[ak + 0][am] = av.x;
        As[ak + 1][am] = av.y;
        As[ak + 2][am] = av.z;
        As[ak + 3][am] = av.w;
        // B tile (scalar, coalesced along n; N may be ragged, e.g. V=50257)
#pragma unroll
        for (int i = 0; i < 4; i++) {
            int idx = tid + i * 256;
            int kk = idx >> 7;
            int n = idx & 127;
            int gn = colBase + n;
            Bs[kk][n] = (gn < N) ? B[(long)(k0 + kk) * N + gn] : 0.0f;
        }
        __syncthreads();

#pragma unroll
        for (int kk = 0; kk < BK; kk++) {
            float4 a0 = *(const float4*)&As[kk][tr * 8];
            float4 a1 = *(const float4*)&As[kk][tr * 8 + 4];
            float4 b0 = *(const float4*)&Bs[kk][tc * 8];
            float4 b1 = *(const float4*)&Bs[kk][tc * 8 + 4];
            float a[8] = {a0.x, a0.y, a0.z, a0.w, a1.x, a1.y, a1.z, a1.w};
            float b[8] = {b0.x, b0.y, b0.z, b0.w, b1.x, b1.y, b1.z, b1.w};
#pragma unroll
            for (int i = 0; i < 8; i++)
#pragma unroll
                for (int j = 0; j < 8; j++) acc[i][j] = fmaf(a[i], b[j], acc[i][j]);
        }
        __syncthreads();
    }

#pragma unroll
    for (int i = 0; i < 8; i++) {
        int row = rowBase + tr * 8 + i;
#pragma unroll
        for (int j = 0; j < 8; j++) {
            int col = colBase + tc * 8 + j;
            if (col < N) {
                float v = acc[i][j];
                if (MODE == 0) {
                    Cmat[(long)z * sC + (long)row * N + col] = v;
                } else if (MODE == 1) {
                    Cmat[(long)z * sC + (long)row * N + col] = gelu_f(v);
                } else if (MODE == 2) {
                    float mv = mask[(long)row * moeE + z];
                    Cmat[(long)row * moeE * moeC + (long)z * moeC + col] = mv * v;
                } else if (MODE == 4) {
                    Cmat[(long)row * N + col] += v;
                }
            }
        }
    }
}

// ---------------- small kernels ----------------
__global__ void embed_kernel(const int* __restrict__ ids, const float* __restrict__ emb,
                             float* __restrict__ hs) {
    int t = blockIdx.x, c = threadIdx.x;
    hs[t * C_ + c] = emb[(size_t)ids[t] * C_ + c];
}

__global__ void layernorm_k(const float* __restrict__ in, const float* __restrict__ w,
                            const float* __restrict__ b, float* __restrict__ out) {
    int t = blockIdx.x, c = threadIdx.x;
    __shared__ float red[256];
    float x = in[t * C_ + c];
    red[c] = x;
    __syncthreads();
    for (int s = 128; s > 0; s >>= 1) { if (c < s) red[c] += red[c + s]; __syncthreads(); }
    float mu = red[0] * (1.0f / C_);
    __syncthreads();
    float d = x - mu;
    red[c] = d * d;
    __syncthreads();
    for (int s = 128; s > 0; s >>= 1) { if (c < s) red[c] += red[c + s]; __syncthreads(); }
    float var = red[0] * (1.0f / C_);
    out[t * C_ + c] = d * rsqrtf(var + 1e-5f) * w[c] + b[c];
}

__global__ void attn_scores(const float* __restrict__ q, const float* __restrict__ k,
                            float* __restrict__ attn) {
    int bh = blockIdx.z;
    int b = bh / H_, h = bh % H_;
    int qt = blockIdx.y * 32, kt = blockIdx.x * 32;
    int ty = threadIdx.y, tx = threadIdx.x;
    int qi = qt + ty, ki = kt + tx;
    size_t oidx = ((size_t)bh * T_ + qi) * T_ + ki;
    if (kt > qt + 31) {             // tile entirely above diagonal
        attn[oidx] = -1e30f;
        return;
    }
    __shared__ float qs[32][33], ks[32][33];
    qs[ty][tx] = q[(size_t)(b * T_ + qt + ty) * C_ + h * D_ + tx];
    ks[ty][tx] = k[(size_t)(b * T_ + kt + ty) * C_ + h * D_ + tx];
    __syncthreads();
    float s;
    if (ki <= qi) {
        float a = 0.0f;
#pragma unroll
        for (int d = 0; d < 32; d++) a = fmaf(qs[ty][d], ks[tx][d], a);
        s = a * 0.17677669529663687f;   // 1/sqrt(32)
    } else {
        s = -1e30f;
    }
    attn[oidx] = s;
}

__global__ void softmax1024(float* __restrict__ attn) {
    size_t row = blockIdx.x;
    float* p = attn + row * 1024;
    int c = threadIdx.x;
    __shared__ float red[256];
    float v[4];
    float m = -INFINITY;
#pragma unroll
    for (int i = 0; i < 4; i++) { v[i] = p[c + 256 * i]; m = fmaxf(m, v[i]); }
    red[c] = m;
    __syncthreads();
    for (int s = 128; s > 0; s >>= 1) { if (c < s) red[c] = fmaxf(red[c], red[c + s]); __syncthreads(); }
    m = red[0];
    __syncthreads();
    float s = 0.0f;
#pragma unroll
    for (int i = 0; i < 4; i++) { v[i] = expf(v[i] - m); s += v[i]; }
    red[c] = s;
    __syncthreads();
    for (int st = 128; st > 0; st >>= 1) { if (c < st) red[c] += red[c + st]; __syncthreads(); }
    float inv = 1.0f / red[0];
#pragma unroll
    for (int i = 0; i < 4; i++) p[c + 256 * i] = v[i] * inv;
}

__global__ void attn_av(const float* __restrict__ attn, const float* __restrict__ v,
                        float* __restrict__ ao) {
    int bh = blockIdx.y;
    int b = bh / H_, h = bh % H_;
    int d = threadIdx.x % 32;
    int qi = threadIdx.x / 32;                  // 0..7 (one warp per q row)
    int q = blockIdx.x * 8 + qi;
    const float* arow = attn + ((size_t)bh * T_ + q) * T_;
    float acc = 0.0f;
    for (int k = 0; k < T_; k++)
        acc = fmaf(arow[k], v[(size_t)(b * T_ + k) * C_ + h * D_ + d], acc);
    ao[(size_t)(b * T_ + q) * C_ + h * D_ + d] = acc;
}

__global__ void snorm_kernel(const float* __restrict__ sim, float* __restrict__ snorm) {
    int e = threadIdx.x;
    float ss = 0.0f;
    for (int c = 0; c < C_; c++) { float v = sim[c * E_ + e]; ss += v * v; }
    snorm[e] = sqrtf(ss);
}

__global__ void gating_kernel(const float* __restrict__ xt, const float* __restrict__ sim,
                              const float* __restrict__ gates, const float* __restrict__ snorm,
                              float* __restrict__ pre_out, float* __restrict__ amask_out,
                              float* __restrict__ rw) {
    int t = blockIdx.x;
    int lane = threadIdx.x;   // 32 threads, one per expert
    const unsigned FULL = 0xffffffffu;

    // token L2 norm
    float ss = 0.0f;
#pragma unroll
    for (int i = 0; i < 8; i++) { float v = xt[t * C_ + lane + i * 32]; ss += v * v; }
#pragma unroll
    for (int o = 16; o; o >>= 1) ss += __shfl_xor_sync(FULL, ss, o);
    float xnorm = fmaxf(sqrtf(ss), 1e-12f);

    // cosine-similarity logit for this expert
    float dot = 0.0f;
    for (int c = 0; c < C_; c++) dot = fmaf(xt[t * C_ + c], sim[c * E_ + lane], dot);
    float logit = dot / (xnorm * fmaxf(snorm[lane], 1e-12f));

    float sig = 1.0f / (1.0f + expf(-gates[lane]));
    float pre = logit - sig;
    pre_out[t * E_ + lane] = pre;

    float gated = fmaxf(pre, 0.0f);
    bool active = pre > 0.0f;
    unsigned bal = __ballot_sync(FULL, active);
    bool sel;
    if (bal == 0u) {
        // fallback: top-(E/2) of raw logits, jax top_k tie-break (lower index wins)
        int rank = 0;
        float my = logit;
#pragma unroll
        for (int j = 0; j < 32; j++) {
            float lj = __shfl_sync(FULL, my, j);
            if (lj > my || (lj == my && j < lane)) rank++;
        }
        sel = rank < (E_ / 2);
    } else {
        sel = active;
    }
    amask_out[t * E_ + lane] = sel ? 1.0f : 0.0f;

    const float NEGV = -3.3895313892515355e38f;   // -bf16 max
    float gl = sel ? gated : NEGV;
    float m = gl;
#pragma unroll
    for (int o = 16; o; o >>= 1) m = fmaxf(m, __shfl_xor_sync(FULL, m, o));
    float ex = expf(gl - m);
    float s = ex;
#pragma unroll
    for (int o = 16; o; o >>= 1) s += __shfl_xor_sync(FULL, s, o);
    rw[t * E_ + lane] = ex / s;
}

__global__ void moe_reduce(const float* __restrict__ rw, const float* __restrict__ feo,
                           float* __restrict__ hs) {
    int t = blockIdx.x, c = threadIdx.x;
    float acc = 0.0f;
#pragma unroll
    for (int e = 0; e < E_; e++)
        acc = fmaf(rw[t * E_ + e], feo[((size_t)t * E_ + e) * C_ + c], acc);
    hs[t * C_ + c] += acc;
}

// ---------------- launcher ----------------
extern "C" void kernel_launch(void* const* d_in, const int* in_sizes, int n_in,
                              void* d_out, int out_size) {
    const int*   ids   = (const int*)d_in[0];
    const float* emb   = (const float*)d_in[1];
    const float* wq    = (const float*)d_in[2];
    const float* wk    = (const float*)d_in[3];
    const float* wv    = (const float*)d_in[4];
    const float* wo    = (const float*)d_in[5];
    const float* ln1w  = (const float*)d_in[6];
    const float* ln1b  = (const float*)d_in[7];
    const float* ln2w  = (const float*)d_in[8];
    const float* ln2b  = (const float*)d_in[9];
    const float* sim   = (const float*)d_in[10];
    const float* gates = (const float*)d_in[11];
    const float* w1    = (const float*)d_in[12];
    const float* w2    = (const float*)d_in[13];
    const float* lmh   = (const float*)d_in[14];

    float* out = (float*)d_out;
    float* out_logits = out;                                   // B*T*V
    float* out_feo    = out_logits + (size_t)B_ * T_ * V_;     // N*E*C
    float* out_pre    = out_feo + (size_t)N_ * E_ * C_;        // N*E
    float* out_mask   = out_pre + (size_t)N_ * E_;             // N*E

    float *hs, *ln, *qb, *kb, *vb, *ao, *attn, *Hbuf, *rw, *snorm;
    cudaGetSymbolAddress((void**)&hs, g_hs);
    cudaGetSymbolAddress((void**)&ln, g_ln);
    cudaGetSymbolAddress((void**)&qb, g_q);
    cudaGetSymbolAddress((void**)&kb, g_k);
    cudaGetSymbolAddress((void**)&vb, g_v);
    cudaGetSymbolAddress((void**)&ao, g_ao);
    cudaGetSymbolAddress((void**)&attn, g_attn);
    cudaGetSymbolAddress((void**)&Hbuf, g_Hbuf);
    cudaGetSymbolAddress((void**)&rw, g_rw);
    cudaGetSymbolAddress((void**)&snorm, g_snorm);

    snorm_kernel<<<1, 32>>>(sim, snorm);
    embed_kernel<<<N_, 256>>>(ids, emb, hs);
    layernorm_k<<<N_, 256>>>(hs, ln1w, ln1b, ln);

    dim3 gProj(2, 16, 1);   // N=256, M=2048
    sgemm128<0><<<gProj, 256>>>(ln, wq, qb, N_, C_, C_, 0, 0, 0, nullptr, 0, 0);
    sgemm128<0><<<gProj, 256>>>(ln, wk, kb, N_, C_, C_, 0, 0, 0, nullptr, 0, 0);
    sgemm128<0><<<gProj, 256>>>(ln, wv, vb, N_, C_, C_, 0, 0, 0, nullptr, 0, 0);

    attn_scores<<<dim3(32, 32, B_ * H_), dim3(32, 32)>>>(qb, kb, attn);
    softmax1024<<<B_ * H_ * T_, 256>>>(attn);
    attn_av<<<dim3(T_ / 8, B_ * H_), 256>>>(attn, vb, ao);

    sgemm128<4><<<gProj, 256>>>(ao, wo, hs, N_, C_, C_, 0, 0, 0, nullptr, 0, 0);  // hs += ao@wo

    layernorm_k<<<N_, 256>>>(hs, ln2w, ln2b, ln);
    gating_kernel<<<N_, 32>>>(ln, sim, gates, snorm, out_pre, out_mask, rw);

    // MoE up: per-expert GEMM [2048,256]@[256,1024] -> gelu -> Hbuf
    sgemm128<1><<<dim3(8, 16, E_), 256>>>(ln, w1, Hbuf, N_, F_, C_,
                                          0, (long)C_ * F_, (long)N_ * F_, nullptr, 0, 0);
    // MoE down: per-expert GEMM [2048,1024]@[1024,256] -> *mask -> full_expert_outputs
    sgemm128<2><<<dim3(2, 16, E_), 256>>>(Hbuf, w2, out_feo, N_, C_, F_,
                                          (long)N_ * F_, (long)F_ * C_, 0, out_mask, E_, C_);

    moe_reduce<<<N_, 256>>>(rw, out_feo, hs);

    // LM head: [2048,256]@[256,50257]
    sgemm128<0><<<dim3((V_ + 127) / 128, 16, 1), 256>>>(hs, lmh, out_logits, N_, V_, C_,
                                                        0, 0, 0, nullptr, 0, 0);
}

// round 7
// speedup vs baseline: 2.8412x; 2.8412x over previous
#include <cuda_runtime.h>
#include <cuda_bf16.h>
#include <math.h>

#define B_ 2
#define T_ 1024
#define C_ 256
#define F_ 1024
#define E_ 32
#define V_ 50257
#define H_ 8
#define D_ 32
#define N_ 2048

// ---------------- scratch (static device globals; no allocations) ----------------
__device__ float g_hs[N_ * C_];
__device__ float g_ln[N_ * C_];
__device__ float g_q[N_ * C_];
__device__ float g_k[N_ * C_];
__device__ float g_v[N_ * C_];
__device__ float g_ao[N_ * C_];
__device__ float g_attn[(size_t)B_ * H_ * T_ * T_];
__device__ float g_Hbuf[67108864];       // E * N * F compact H (256 MB)
__device__ float g_rw[N_ * E_];
__device__ float g_snorm[E_];
__device__ int   g_counts[E_];
__device__ int   g_lists[E_ * N_];

__device__ __forceinline__ float gelu_f(float x) {
    return 0.5f * x * (1.0f + erff(x * 0.70710678118654752440f));
}

__device__ __forceinline__ unsigned f2tf32(float x) {
    unsigned r;
    asm("cvt.rna.tf32.f32 %0, %1;" : "=r"(r) : "f"(x));
    return r;
}

// =================== tf32 tensor-core GEMM, 128x128 tile, BK=16 ====================
// 8 warps (2m x 4n), warp tile 64x32, mma.m16n8k8 tf32.
// MODE 0: dense  C[M,N] = A[M,K] @ B[K,N]   (LM head; ragged N, SCALAR B loads --
//         row stride N=50257 floats is not 16B-aligned, float4 would trap)
// MODE 1: sparse up: rows gathered via lists[e], C = gelu(acc) into compact H
// MODE 2: sparse down: A = compact H rows, C scattered to feo[t][e][:]
template <int MODE>
__global__ __launch_bounds__(256, 2) void gemm_tf32(
    const float* __restrict__ A, const float* __restrict__ Bg, float* __restrict__ Cg,
    int M, int N, int K, long strideB, long strideH,
    const int* __restrict__ lists, const int* __restrict__ counts)
{
    const int BM = 128, BN = 128, BK = 16;
    int e = blockIdx.z;
    int Me = (MODE == 0) ? M : counts[e];
    int rowBase = blockIdx.y * BM;
    if (MODE != 0 && rowBase >= Me) return;
    int colBase = blockIdx.x * BN;

    const float* Bp = (MODE == 0) ? Bg : (Bg + (long)e * strideB);
    const float* Ap = (MODE == 2) ? (A + (long)e * strideH) : A;

    __shared__ unsigned As[BK][BM + 8];
    __shared__ unsigned Bs[BK][BN + 8];

    int tid = threadIdx.x;
    int lane = tid & 31;
    int warp = tid >> 5;
    int m0 = (warp >> 2) * 64;
    int n0w = (warp & 3) * 32;
    int g = lane >> 2;   // group id 0..7
    int tg = lane & 3;   // thread-in-group 0..3

    float acc[4][4][4];
#pragma unroll
    for (int i = 0; i < 4; i++)
#pragma unroll
        for (int j = 0; j < 4; j++)
#pragma unroll
            for (int c = 0; c < 4; c++) acc[i][j][c] = 0.0f;

    // A loader: thread -> (m = tid/2, k-chunk = (tid&1)*8)
    int am = tid >> 1;
    int kc = (tid & 1) * 8;
    int arow;
    if (MODE == 1) {
        int i = rowBase + am;
        arow = (i < Me) ? lists[e * N_ + i] : 0;
    } else {
        arow = rowBase + am;
    }
    const float* Arow = Ap + (long)arow * K;

    // B loader: thread -> (n4 = lane*4, k = warp and warp+8)
    int bn = lane * 4;
    int bk = warp;

    for (int k0 = 0; k0 < K; k0 += BK) {
        float4 a0 = *(const float4*)(Arow + k0 + kc);
        float4 a1 = *(const float4*)(Arow + k0 + kc + 4);
        As[kc + 0][am] = f2tf32(a0.x);
        As[kc + 1][am] = f2tf32(a0.y);
        As[kc + 2][am] = f2tf32(a0.z);
        As[kc + 3][am] = f2tf32(a0.w);
        As[kc + 4][am] = f2tf32(a1.x);
        As[kc + 5][am] = f2tf32(a1.y);
        As[kc + 6][am] = f2tf32(a1.z);
        As[kc + 7][am] = f2tf32(a1.w);

#pragma unroll
        for (int h = 0; h < 2; h++) {
            int kk = bk + h * 8;
            int gcol = colBase + bn;
            const float* bsrc = Bp + (long)(k0 + kk) * N + gcol;
            float x0, x1, x2, x3;
            if (MODE == 0) {
                // ragged / misaligned N: scalar loads only
                x0 = (gcol + 0 < N) ? bsrc[0] : 0.0f;
                x1 = (gcol + 1 < N) ? bsrc[1] : 0.0f;
                x2 = (gcol + 2 < N) ? bsrc[2] : 0.0f;
                x3 = (gcol + 3 < N) ? bsrc[3] : 0.0f;
            } else {
                // N multiple of 128, 16B-aligned rows
                float4 bv = *(const float4*)bsrc;
                x0 = bv.x; x1 = bv.y; x2 = bv.z; x3 = bv.w;
            }
            Bs[kk][bn + 0] = f2tf32(x0);
            Bs[kk][bn + 1] = f2tf32(x1);
            Bs[kk][bn + 2] = f2tf32(x2);
            Bs[kk][bn + 3] = f2tf32(x3);
        }
        __syncthreads();

#pragma unroll
        for (int ks = 0; ks < BK; ks += 8) {
            unsigned af[4][4];
#pragma unroll
            for (int mi = 0; mi < 4; mi++) {
                int r = m0 + mi * 16 + g;
                af[mi][0] = As[ks + tg][r];
                af[mi][1] = As[ks + tg][r + 8];
                af[mi][2] = As[ks + tg + 4][r];
                af[mi][3] = As[ks + tg + 4][r + 8];
            }
            unsigned bf[4][2];
#pragma unroll
            for (int ni = 0; ni < 4; ni++) {
                int c = n0w + ni * 8 + g;
                bf[ni][0] = Bs[ks + tg][c];
                bf[ni][1] = Bs[ks + tg + 4][c];
            }
#pragma unroll
            for (int mi = 0; mi < 4; mi++)
#pragma unroll
                for (int ni = 0; ni < 4; ni++) {
                    asm volatile(
                        "mma.sync.aligned.m16n8k8.row.col.f32.tf32.tf32.f32 "
                        "{%0,%1,%2,%3}, {%4,%5,%6,%7}, {%8,%9}, {%0,%1,%2,%3};\n"
                        : "+f"(acc[mi][ni][0]), "+f"(acc[mi][ni][1]),
                          "+f"(acc[mi][ni][2]), "+f"(acc[mi][ni][3])
                        : "r"(af[mi][0]), "r"(af[mi][1]), "r"(af[mi][2]), "r"(af[mi][3]),
                          "r"(bf[ni][0]), "r"(bf[ni][1]));
                }
        }
        __syncthreads();
    }

    // epilogue
#pragma unroll
    for (int mi = 0; mi < 4; mi++) {
#pragma unroll
        for (int half = 0; half < 2; half++) {
            int rloc = m0 + mi * 16 + g + half * 8;
            int i = rowBase + rloc;
#pragma unroll
            for (int ni = 0; ni < 4; ni++) {
                float c0 = acc[mi][ni][half * 2 + 0];
                float c1 = acc[mi][ni][half * 2 + 1];
                int col = colBase + n0w + ni * 8 + 2 * tg;
                if (MODE == 0) {
                    if (col < N)     Cg[(long)i * N + col] = c0;
                    if (col + 1 < N) Cg[(long)i * N + col + 1] = c1;
                } else if (MODE == 1) {
                    if (i < Me) {
                        float* dst = Cg + (long)e * strideH + (long)i * F_ + col;
                        dst[0] = gelu_f(c0);
                        dst[1] = gelu_f(c1);
                    }
                } else {
                    if (i < Me) {
                        int t = lists[e * N_ + i];
                        float* dst = Cg + ((long)t * E_ + e) * C_ + col;
                        dst[0] = c0;
                        dst[1] = c1;
                    }
                }
            }
        }
    }
}

// =================== fp32 SGEMM (attention path, precision-critical) ====================
template <int MODE>  // 0: C = acc, 4: C += acc
__global__ __launch_bounds__(256) void sgemm128(
    const float* __restrict__ A, const float* __restrict__ B, float* __restrict__ Cmat,
    int M, int N, int K)
{
    const int BM = 128, BN = 128, BK = 8;
    __shared__ float As[BK][BM];
    __shared__ float Bs[BK][BN + 4];

    int tid = threadIdx.x;
    int rowBase = blockIdx.y * BM;
    int colBase = blockIdx.x * BN;
    int tr = tid / 16, tc = tid % 16;

    float acc[8][8];
#pragma unroll
    for (int i = 0; i < 8; i++)
#pragma unroll
        for (int j = 0; j < 8; j++) acc[i][j] = 0.0f;

    int am = tid >> 1;
    int ak = (tid & 1) * 4;

    for (int k0 = 0; k0 < K; k0 += BK) {
        float4 av = *(const float4*)(A + (long)(rowBase + am) * K + k0 + ak);
        As[ak + 0][am] = av.x;
        As[ak + 1][am] = av.y;
        As[ak + 2][am] = av.z;
        As[ak + 3][am] = av.w;
#pragma unroll
        for (int i = 0; i < 4; i++) {
            int idx = tid + i * 256;
            int kk = idx >> 7;
            int n = idx & 127;
            int gn = colBase + n;
            Bs[kk][n] = (gn < N) ? B[(long)(k0 + kk) * N + gn] : 0.0f;
        }
        __syncthreads();
#pragma unroll
        for (int kk = 0; kk < BK; kk++) {
            float4 a0 = *(const float4*)&As[kk][tr * 8];
            float4 a1 = *(const float4*)&As[kk][tr * 8 + 4];
            float4 b0 = *(const float4*)&Bs[kk][tc * 8];
            float4 b1 = *(const float4*)&Bs[kk][tc * 8 + 4];
            float a[8] = {a0.x, a0.y, a0.z, a0.w, a1.x, a1.y, a1.z, a1.w};
            float b[8] = {b0.x, b0.y, b0.z, b0.w, b1.x, b1.y, b1.z, b1.w};
#pragma unroll
            for (int i = 0; i < 8; i++)
#pragma unroll
                for (int j = 0; j < 8; j++) acc[i][j] = fmaf(a[i], b[j], acc[i][j]);
        }
        __syncthreads();
    }

#pragma unroll
    for (int i = 0; i < 8; i++) {
        int row = rowBase + tr * 8 + i;
#pragma unroll
        for (int j = 0; j < 8; j++) {
            int col = colBase + tc * 8 + j;
            if (col < N) {
                if (MODE == 0) Cmat[(long)row * N + col] = acc[i][j];
                else           Cmat[(long)row * N + col] += acc[i][j];
            }
        }
    }
}

// fused Q/K/V projection: z selects weight/output (N=K=256 fixed)
__global__ __launch_bounds__(256) void sgemm_qkv(
    const float* __restrict__ A,
    const float* __restrict__ Wq, const float* __restrict__ Wk, const float* __restrict__ Wv,
    float* __restrict__ Oq, float* __restrict__ Ok, float* __restrict__ Ov)
{
    const int BM = 128, BN = 128, BK = 8, K = 256, N = 256;
    int z = blockIdx.z;
    const float* B = (z == 0) ? Wq : (z == 1) ? Wk : Wv;
    float* Cmat = (z == 0) ? Oq : (z == 1) ? Ok : Ov;

    __shared__ float As[BK][BM];
    __shared__ float Bs[BK][BN + 4];

    int tid = threadIdx.x;
    int rowBase = blockIdx.y * BM;
    int colBase = blockIdx.x * BN;
    int tr = tid / 16, tc = tid % 16;

    float acc[8][8];
#pragma unroll
    for (int i = 0; i < 8; i++)
#pragma unroll
        for (int j = 0; j < 8; j++) acc[i][j] = 0.0f;

    int am = tid >> 1;
    int ak = (tid & 1) * 4;

    for (int k0 = 0; k0 < K; k0 += BK) {
        float4 av = *(const float4*)(A + (long)(rowBase + am) * K + k0 + ak);
        As[ak + 0][am] = av.x;
        As[ak + 1][am] = av.y;
        As[ak + 2][am] = av.z;
        As[ak + 3][am] = av.w;
#pragma unroll
        for (int i = 0; i < 4; i++) {
            int idx = tid + i * 256;
            int kk = idx >> 7;
            int n = idx & 127;
            Bs[kk][n] = B[(long)(k0 + kk) * N + colBase + n];
        }
        __syncthreads();
#pragma unroll
        for (int kk = 0; kk < BK; kk++) {
            float4 a0 = *(const float4*)&As[kk][tr * 8];
            float4 a1 = *(const float4*)&As[kk][tr * 8 + 4];
            float4 b0 = *(const float4*)&Bs[kk][tc * 8];
            float4 b1 = *(const float4*)&Bs[kk][tc * 8 + 4];
            float a[8] = {a0.x, a0.y, a0.z, a0.w, a1.x, a1.y, a1.z, a1.w};
            float b[8] = {b0.x, b0.y, b0.z, b0.w, b1.x, b1.y, b1.z, b1.w};
#pragma unroll
            for (int i = 0; i < 8; i++)
#pragma unroll
                for (int j = 0; j < 8; j++) acc[i][j] = fmaf(a[i], b[j], acc[i][j]);
        }
        __syncthreads();
    }
#pragma unroll
    for (int i = 0; i < 8; i++) {
        int row = rowBase + tr * 8 + i;
#pragma unroll
        for (int j = 0; j < 8; j++)
            Cmat[(long)row * N + colBase + tc * 8 + j] = acc[i][j];
    }
}

// ---------------- small kernels ----------------
__global__ void embed_kernel(const int* __restrict__ ids, const float* __restrict__ emb,
                             float* __restrict__ hs) {
    int t = blockIdx.x, c = threadIdx.x;
    hs[t * C_ + c] = emb[(size_t)ids[t] * C_ + c];
}

__global__ void layernorm_k(const float* __restrict__ in, const float* __restrict__ w,
                            const float* __restrict__ b, float* __restrict__ out) {
    int t = blockIdx.x, c = threadIdx.x;
    __shared__ float red[256];
    float x = in[t * C_ + c];
    red[c] = x;
    __syncthreads();
    for (int s = 128; s > 0; s >>= 1) { if (c < s) red[c] += red[c + s]; __syncthreads(); }
    float mu = red[0] * (1.0f / C_);
    __syncthreads();
    float d = x - mu;
    red[c] = d * d;
    __syncthreads();
    for (int s = 128; s > 0; s >>= 1) { if (c < s) red[c] += red[c + s]; __syncthreads(); }
    float var = red[0] * (1.0f / C_);
    out[t * C_ + c] = d * rsqrtf(var + 1e-5f) * w[c] + b[c];
}

__global__ void attn_scores(const float* __restrict__ q, const float* __restrict__ k,
                            float* __restrict__ attn) {
    int bh = blockIdx.z;
    int b = bh / H_, h = bh % H_;
    int qt = blockIdx.y * 32, kt = blockIdx.x * 32;
    int ty = threadIdx.y, tx = threadIdx.x;
    int qi = qt + ty, ki = kt + tx;
    size_t oidx = ((size_t)bh * T_ + qi) * T_ + ki;
    if (kt > qt + 31) { attn[oidx] = -1e30f; return; }
    __shared__ float qs[32][33], ks[32][33];
    qs[ty][tx] = q[(size_t)(b * T_ + qt + ty) * C_ + h * D_ + tx];
    ks[ty][tx] = k[(size_t)(b * T_ + kt + ty) * C_ + h * D_ + tx];
    __syncthreads();
    float s;
    if (ki <= qi) {
        float a = 0.0f;
#pragma unroll
        for (int d = 0; d < 32; d++) a = fmaf(qs[ty][d], ks[tx][d], a);
        s = a * 0.17677669529663687f;
    } else {
        s = -1e30f;
    }
    attn[oidx] = s;
}

__global__ void softmax1024(float* __restrict__ attn) {
    size_t row = blockIdx.x;
    float* p = attn + row * 1024;
    int c = threadIdx.x;
    __shared__ float red[256];
    float v[4];
    float m = -INFINITY;
#pragma unroll
    for (int i = 0; i < 4; i++) { v[i] = p[c + 256 * i]; m = fmaxf(m, v[i]); }
    red[c] = m;
    __syncthreads();
    for (int s = 128; s > 0; s >>= 1) { if (c < s) red[c] = fmaxf(red[c], red[c + s]); __syncthreads(); }
    m = red[0];
    __syncthreads();
    float s = 0.0f;
#pragma unroll
    for (int i = 0; i < 4; i++) { v[i] = expf(v[i] - m); s += v[i]; }
    red[c] = s;
    __syncthreads();
    for (int st = 128; st > 0; st >>= 1) { if (c < st) red[c] += red[c + st]; __syncthreads(); }
    float inv = 1.0f / red[0];
#pragma unroll
    for (int i = 0; i < 4; i++) p[c + 256 * i] = v[i] * inv;
}

__global__ void attn_av(const float* __restrict__ attn, const float* __restrict__ v,
                        float* __restrict__ ao) {
    int bh = blockIdx.y;
    int b = bh / H_, h = bh % H_;
    int d = threadIdx.x % 32;
    int qi = threadIdx.x / 32;
    int q = blockIdx.x * 8 + qi;
    const float* arow = attn + ((size_t)bh * T_ + q) * T_;
    float acc = 0.0f;
    for (int k = 0; k < T_; k++)
        acc = fmaf(arow[k], v[(size_t)(b * T_ + k) * C_ + h * D_ + d], acc);
    ao[(size_t)(b * T_ + q) * C_ + h * D_ + d] = acc;
}

__global__ void snorm_kernel(const float* __restrict__ sim, float* __restrict__ snorm) {
    int e = threadIdx.x;
    float ss = 0.0f;
    for (int c = 0; c < C_; c++) { float v = sim[c * E_ + e]; ss += v * v; }
    snorm[e] = sqrtf(ss);
}

__global__ void gating_kernel(const float* __restrict__ xt, const float* __restrict__ sim,
                              const float* __restrict__ gates, const float* __restrict__ snorm,
                              float* __restrict__ pre_out, float* __restrict__ amask_out,
                              float* __restrict__ rw) {
    int t = blockIdx.x;
    int lane = threadIdx.x;
    const unsigned FULL = 0xffffffffu;

    float ss = 0.0f;
#pragma unroll
    for (int i = 0; i < 8; i++) { float v = xt[t * C_ + lane + i * 32]; ss += v * v; }
#pragma unroll
    for (int o = 16; o; o >>= 1) ss += __shfl_xor_sync(FULL, ss, o);
    float xnorm = fmaxf(sqrtf(ss), 1e-12f);

    float dot = 0.0f;
    for (int c = 0; c < C_; c++) dot = fmaf(xt[t * C_ + c], sim[c * E_ + lane], dot);
    float logit = dot / (xnorm * fmaxf(snorm[lane], 1e-12f));

    float sig = 1.0f / (1.0f + expf(-gates[lane]));
    float pre = logit - sig;
    pre_out[t * E_ + lane] = pre;

    float gated = fmaxf(pre, 0.0f);
    bool active = pre > 0.0f;
    unsigned bal = __ballot_sync(FULL, active);
    bool sel;
    if (bal == 0u) {
        int rank = 0;
        float my = logit;
#pragma unroll
        for (int j = 0; j < 32; j++) {
            float lj = __shfl_sync(FULL, my, j);
            if (lj > my || (lj == my && j < lane)) rank++;
        }
        sel = rank < (E_ / 2);
    } else {
        sel = active;
    }
    amask_out[t * E_ + lane] = sel ? 1.0f : 0.0f;

    const float NEGV = -3.3895313892515355e38f;
    float gl = sel ? gated : NEGV;
    float m = gl;
#pragma unroll
    for (int o = 16; o; o >>= 1) m = fmaxf(m, __shfl_xor_sync(FULL, m, o));
    float ex = expf(gl - m);
    float s = ex;
#pragma unroll
    for (int o = 16; o; o >>= 1) s += __shfl_xor_sync(FULL, s, o);
    rw[t * E_ + lane] = ex / s;
}

// deterministic per-expert token compaction (1 warp per expert)
__global__ void build_lists(const float* __restrict__ mask, int* __restrict__ counts,
                            int* __restrict__ lists) {
    int e = blockIdx.x;
    int lane = threadIdx.x;
    int cnt = 0;
    for (int base = 0; base < N_; base += 32) {
        int t = base + lane;
        bool a = mask[t * E_ + e] > 0.5f;
        unsigned bal = __ballot_sync(0xffffffffu, a);
        int pos = cnt + __popc(bal & ((1u << lane) - 1u));
        if (a) lists[e * N_ + pos] = t;
        cnt += __popc(bal);
    }
    if (lane == 0) counts[e] = cnt;
}

__global__ void zero_feo(float4* __restrict__ p) {
    size_t i = (size_t)blockIdx.x * blockDim.x + threadIdx.x;
    p[i] = make_float4(0.f, 0.f, 0.f, 0.f);
}

__global__ void moe_reduce(const float* __restrict__ rw, const float* __restrict__ feo,
                           float* __restrict__ hs) {
    int t = blockIdx.x, c = threadIdx.x;
    float acc = 0.0f;
#pragma unroll
    for (int e = 0; e < E_; e++)
        acc = fmaf(rw[t * E_ + e], feo[((size_t)t * E_ + e) * C_ + c], acc);
    hs[t * C_ + c] += acc;
}

// ---------------- launcher ----------------
extern "C" void kernel_launch(void* const* d_in, const int* in_sizes, int n_in,
                              void* d_out, int out_size) {
    const int*   ids   = (const int*)d_in[0];
    const float* emb   = (const float*)d_in[1];
    const float* wq    = (const float*)d_in[2];
    const float* wk    = (const float*)d_in[3];
    const float* wv    = (const float*)d_in[4];
    const float* wo    = (const float*)d_in[5];
    const float* ln1w  = (const float*)d_in[6];
    const float* ln1b  = (const float*)d_in[7];
    const float* ln2w  = (const float*)d_in[8];
    const float* ln2b  = (const float*)d_in[9];
    const float* sim   = (const float*)d_in[10];
    const float* gates = (const float*)d_in[11];
    const float* w1    = (const float*)d_in[12];
    const float* w2    = (const float*)d_in[13];
    const float* lmh   = (const float*)d_in[14];

    float* out = (float*)d_out;
    float* out_logits = out;
    float* out_feo    = out_logits + (size_t)B_ * T_ * V_;
    float* out_pre    = out_feo + (size_t)N_ * E_ * C_;
    float* out_mask   = out_pre + (size_t)N_ * E_;

    float *hs, *ln, *qb, *kb, *vb, *ao, *attn, *Hbuf, *rw, *snorm;
    int *counts, *lists;
    cudaGetSymbolAddress((void**)&hs, g_hs);
    cudaGetSymbolAddress((void**)&ln, g_ln);
    cudaGetSymbolAddress((void**)&qb, g_q);
    cudaGetSymbolAddress((void**)&kb, g_k);
    cudaGetSymbolAddress((void**)&vb, g_v);
    cudaGetSymbolAddress((void**)&ao, g_ao);
    cudaGetSymbolAddress((void**)&attn, g_attn);
    cudaGetSymbolAddress((void**)&Hbuf, g_Hbuf);
    cudaGetSymbolAddress((void**)&rw, g_rw);
    cudaGetSymbolAddress((void**)&snorm, g_snorm);
    cudaGetSymbolAddress((void**)&counts, g_counts);
    cudaGetSymbolAddress((void**)&lists, g_lists);

    snorm_kernel<<<1, 32>>>(sim, snorm);
    embed_kernel<<<N_, 256>>>(ids, emb, hs);
    layernorm_k<<<N_, 256>>>(hs, ln1w, ln1b, ln);

    // fused QKV (fp32, precision-critical path)
    sgemm_qkv<<<dim3(2, 16, 3), 256>>>(ln, wq, wk, wv, qb, kb, vb);

    attn_scores<<<dim3(32, 32, B_ * H_), dim3(32, 32)>>>(qb, kb, attn);
    softmax1024<<<B_ * H_ * T_, 256>>>(attn);
    attn_av<<<dim3(T_ / 8, B_ * H_), 256>>>(attn, vb, ao);

    sgemm128<4><<<dim3(2, 16), 256>>>(ao, wo, hs, N_, C_, C_);  // hs += ao@wo

    layernorm_k<<<N_, 256>>>(hs, ln2w, ln2b, ln);
    gating_kernel<<<N_, 32>>>(ln, sim, gates, snorm, out_pre, out_mask, rw);
    build_lists<<<E_, 32>>>(out_mask, counts, lists);

    // zero full_expert_outputs (inactive pairs must be exactly 0)
    zero_feo<<<(N_ * E_ * C_ / 4) / 256, 256>>>((float4*)out_feo);

    // sparse MoE up: gather active tokens per expert, gelu, compact H
    gemm_tf32<1><<<dim3(F_ / 128, N_ / 128, E_), 256>>>(
        ln, w1, Hbuf, 0, F_, C_, (long)C_ * F_, (long)N_ * F_, lists, counts);
    // sparse MoE down: compact H -> scatter into feo
    gemm_tf32<2><<<dim3(C_ / 128, N_ / 128, E_), 256>>>(
        Hbuf, w2, out_feo, 0, C_, F_, (long)F_ * C_, (long)N_ * F_, lists, counts);

    moe_reduce<<<N_, 256>>>(rw, out_feo, hs);

    // LM head (tf32): [2048,256] @ [256,50257]
    gemm_tf32<0><<<dim3((V_ + 127) / 128, N_ / 128, 1), 256>>>(
        hs, lmh, out_logits, N_, V_, C_, 0, 0, nullptr, nullptr);
}

// round 8
// speedup vs baseline: 3.0991x; 1.0908x over previous
#include <cuda_runtime.h>
#include <cuda_bf16.h>
#include <math.h>

#define B_ 2
#define T_ 1024
#define C_ 256
#define F_ 1024
#define E_ 32
#define V_ 50257
#define H_ 8
#define D_ 32
#define N_ 2048

// ---------------- scratch (static device globals; no allocations) ----------------
__device__ float g_hs[N_ * C_];
__device__ float g_ln[N_ * C_];
__device__ float g_q[N_ * C_];
__device__ float g_k[N_ * C_];
__device__ float g_v[N_ * C_];
__device__ float g_ao[N_ * C_];
__device__ float g_attn[(size_t)B_ * H_ * T_ * T_];
__device__ float g_Hbuf[67108864];       // E * N * F compact H (256 MB)
__device__ float g_rw[N_ * E_];
__device__ float g_snorm[E_];
__device__ int   g_counts[E_];
__device__ int   g_lists[E_ * N_];

__device__ __forceinline__ float gelu_f(float x) {
    return 0.5f * x * (1.0f + erff(x * 0.70710678118654752440f));
}

__device__ __forceinline__ unsigned f2tf32(float x) {
    unsigned r;
    asm("cvt.rna.tf32.f32 %0, %1;" : "=r"(r) : "f"(x));
    return r;
}

// =================== tf32 tensor-core GEMM, 128x128 tile, BK=16, double-buffered ====
// 8 warps (2m x 4n), warp tile 64x32, mma.m16n8k8 tf32.
// Software pipeline: global loads for tile k+1 are issued before the mma block of
// tile k (register staging), STS into the alternate smem stage, 1 sync per iter.
// MODE 0: dense  C[M,N] = A[M,K] @ B[K,N]   (LM head; ragged N, SCALAR B loads --
//         row stride N=50257 floats is not 16B-aligned, float4 would trap)
// MODE 1: sparse up: rows gathered via lists[e], C = gelu(acc) into compact H
// MODE 2: sparse down: A = compact H rows, C scattered to feo[t][e][:]
template <int MODE>
__global__ __launch_bounds__(256, 2) void gemm_tf32(
    const float* __restrict__ A, const float* __restrict__ Bg, float* __restrict__ Cg,
    int M, int N, int K, long strideB, long strideH,
    const int* __restrict__ lists, const int* __restrict__ counts)
{
    const int BM = 128, BN = 128, BK = 16;
    int e = blockIdx.z;
    int Me = (MODE == 0) ? M : counts[e];
    int rowBase = blockIdx.y * BM;
    if (MODE != 0 && rowBase >= Me) return;
    int colBase = blockIdx.x * BN;

    const float* Bp = (MODE == 0) ? Bg : (Bg + (long)e * strideB);
    const float* Ap = (MODE == 2) ? (A + (long)e * strideH) : A;

    __shared__ unsigned As[2][BK][BM + 8];
    __shared__ unsigned Bs[2][BK][BN + 8];

    int tid = threadIdx.x;
    int lane = tid & 31;
    int warp = tid >> 5;
    int m0 = (warp >> 2) * 64;
    int n0w = (warp & 3) * 32;
    int g = lane >> 2;   // group id 0..7
    int tg = lane & 3;   // thread-in-group 0..3

    float acc[4][4][4];
#pragma unroll
    for (int i = 0; i < 4; i++)
#pragma unroll
        for (int j = 0; j < 4; j++)
#pragma unroll
            for (int c = 0; c < 4; c++) acc[i][j][c] = 0.0f;

    // A loader: thread -> (m = tid/2, k-chunk = (tid&1)*8)
    int am = tid >> 1;
    int kc = (tid & 1) * 8;
    int arow;
    if (MODE == 1) {
        int i = rowBase + am;
        arow = (i < Me) ? lists[e * N_ + i] : 0;
    } else {
        arow = rowBase + am;
    }
    const float* Arow = Ap + (long)arow * K;

    // B loader: thread -> (n4 = lane*4, k = warp and warp+8)
    int bn = lane * 4;
    int bk = warp;

    unsigned arg[8], brg[8];

#define LOADG_TILE(k0)                                                  \
    {                                                                   \
        float4 a0 = *(const float4*)(Arow + (k0) + kc);                 \
        float4 a1 = *(const float4*)(Arow + (k0) + kc + 4);             \
        arg[0] = f2tf32(a0.x); arg[1] = f2tf32(a0.y);                   \
        arg[2] = f2tf32(a0.z); arg[3] = f2tf32(a0.w);                   \
        arg[4] = f2tf32(a1.x); arg[5] = f2tf32(a1.y);                   \
        arg[6] = f2tf32(a1.z); arg[7] = f2tf32(a1.w);                   \
        {                                                               \
            int gcol = colBase + bn;                                    \
            const float* bsrc0 = Bp + (long)((k0) + bk) * N + gcol;     \
            const float* bsrc1 = Bp + (long)((k0) + bk + 8) * N + gcol; \
            float x0, x1, x2, x3, y0, y1, y2, y3;                       \
            if (MODE == 0) {                                            \
                x0 = (gcol + 0 < N) ? bsrc0[0] : 0.0f;                  \
                x1 = (gcol + 1 < N) ? bsrc0[1] : 0.0f;                  \
                x2 = (gcol + 2 < N) ? bsrc0[2] : 0.0f;                  \
                x3 = (gcol + 3 < N) ? bsrc0[3] : 0.0f;                  \
                y0 = (gcol + 0 < N) ? bsrc1[0] : 0.0f;                  \
                y1 = (gcol + 1 < N) ? bsrc1[1] : 0.0f;                  \
                y2 = (gcol + 2 < N) ? bsrc1[2] : 0.0f;                  \
                y3 = (gcol + 3 < N) ? bsrc1[3] : 0.0f;                  \
            } else {                                                    \
                float4 bv0 = *(const float4*)bsrc0;                     \
                float4 bv1 = *(const float4*)bsrc1;                     \
                x0 = bv0.x; x1 = bv0.y; x2 = bv0.z; x3 = bv0.w;         \
                y0 = bv1.x; y1 = bv1.y; y2 = bv1.z; y3 = bv1.w;         \
            }                                                           \
            brg[0] = f2tf32(x0); brg[1] = f2tf32(x1);                   \
            brg[2] = f2tf32(x2); brg[3] = f2tf32(x3);                   \
            brg[4] = f2tf32(y0); brg[5] = f2tf32(y1);                   \
            brg[6] = f2tf32(y2); brg[7] = f2tf32(y3);                   \
        }                                                               \
    }

#define STS_TILE(bufi)                                                  \
    {                                                                   \
        As[bufi][kc + 0][am] = arg[0];                                  \
        As[bufi][kc + 1][am] = arg[1];                                  \
        As[bufi][kc + 2][am] = arg[2];                                  \
        As[bufi][kc + 3][am] = arg[3];                                  \
        As[bufi][kc + 4][am] = arg[4];                                  \
        As[bufi][kc + 5][am] = arg[5];                                  \
        As[bufi][kc + 6][am] = arg[6];                                  \
        As[bufi][kc + 7][am] = arg[7];                                  \
        Bs[bufi][bk][bn + 0] = brg[0];                                  \
        Bs[bufi][bk][bn + 1] = brg[1];                                  \
        Bs[bufi][bk][bn + 2] = brg[2];                                  \
        Bs[bufi][bk][bn + 3] = brg[3];                                  \
        Bs[bufi][bk + 8][bn + 0] = brg[4];                              \
        Bs[bufi][bk + 8][bn + 1] = brg[5];                              \
        Bs[bufi][bk + 8][bn + 2] = brg[6];                              \
        Bs[bufi][bk + 8][bn + 3] = brg[7];                              \
    }

    LOADG_TILE(0);
    STS_TILE(0);
    __syncthreads();

    int buf = 0;
    for (int k0 = 0; k0 < K; k0 += BK) {
        bool has_next = (k0 + BK) < K;
        if (has_next) LOADG_TILE(k0 + BK);

#pragma unroll
        for (int ks = 0; ks < BK; ks += 8) {
            unsigned af[4][4];
#pragma unroll
            for (int mi = 0; mi < 4; mi++) {
                int r = m0 + mi * 16 + g;
                af[mi][0] = As[buf][ks + tg][r];
                af[mi][1] = As[buf][ks + tg][r + 8];
                af[mi][2] = As[buf][ks + tg + 4][r];
                af[mi][3] = As[buf][ks + tg + 4][r + 8];
            }
            unsigned bf[4][2];
#pragma unroll
            for (int ni = 0; ni < 4; ni++) {
                int c = n0w + ni * 8 + g;
                bf[ni][0] = Bs[buf][ks + tg][c];
                bf[ni][1] = Bs[buf][ks + tg + 4][c];
            }
#pragma unroll
            for (int mi = 0; mi < 4; mi++)
#pragma unroll
                for (int ni = 0; ni < 4; ni++) {
                    asm volatile(
                        "mma.sync.aligned.m16n8k8.row.col.f32.tf32.tf32.f32 "
                        "{%0,%1,%2,%3}, {%4,%5,%6,%7}, {%8,%9}, {%0,%1,%2,%3};\n"
                        : "+f"(acc[mi][ni][0]), "+f"(acc[mi][ni][1]),
                          "+f"(acc[mi][ni][2]), "+f"(acc[mi][ni][3])
                        : "r"(af[mi][0]), "r"(af[mi][1]), "r"(af[mi][2]), "r"(af[mi][3]),
                          "r"(bf[ni][0]), "r"(bf[ni][1]));
                }
        }

        if (has_next) STS_TILE(buf ^ 1);
        __syncthreads();
        buf ^= 1;
    }

    // epilogue
#pragma unroll
    for (int mi = 0; mi < 4; mi++) {
#pragma unroll
        for (int half = 0; half < 2; half++) {
            int rloc = m0 + mi * 16 + g + half * 8;
            int i = rowBase + rloc;
#pragma unroll
            for (int ni = 0; ni < 4; ni++) {
                float c0 = acc[mi][ni][half * 2 + 0];
                float c1 = acc[mi][ni][half * 2 + 1];
                int col = colBase + n0w + ni * 8 + 2 * tg;
                if (MODE == 0) {
                    if (col < N)     Cg[(long)i * N + col] = c0;
                    if (col + 1 < N) Cg[(long)i * N + col + 1] = c1;
                } else if (MODE == 1) {
                    if (i < Me) {
                        float* dst = Cg + (long)e * strideH + (long)i * F_ + col;
                        dst[0] = gelu_f(c0);
                        dst[1] = gelu_f(c1);
                    }
                } else {
                    if (i < Me) {
                        int t = lists[e * N_ + i];
                        float* dst = Cg + ((long)t * E_ + e) * C_ + col;
                        dst[0] = c0;
                        dst[1] = c1;
                    }
                }
            }
        }
    }
#undef LOADG_TILE
#undef STS_TILE
}

// =================== fp32 SGEMM, 64x64 tile, BK=16, double-buffered =================
// Attention-path GEMMs (precision-critical, must stay fp32 with ascending-k fmaf).
// 256 threads, 4x4 per thread. MODE 0: C = acc; MODE 4: C += acc.
template <int MODE>
__global__ __launch_bounds__(256) void sgemm64(
    const float* __restrict__ A, const float* __restrict__ B, float* __restrict__ Cmat,
    int N, int K)
{
    const int BM = 64, BN = 64, BK = 16;
    __shared__ float As[2][BK][BM + 4];
    __shared__ float Bs[2][BK][BN + 4];

    int tid = threadIdx.x;
    int rowBase = blockIdx.y * BM;
    int colBase = blockIdx.x * BN;
    int tr = tid >> 4;        // 0..15
    int tc = tid & 15;        // 0..15

    float acc[4][4];
#pragma unroll
    for (int i = 0; i < 4; i++)
#pragma unroll
        for (int j = 0; j < 4; j++) acc[i][j] = 0.0f;

    // A loader: row = tid&63, kchunk = (tid>>6)*4
    int am = tid & 63;
    int ak = (tid >> 6) * 4;
    const float* Arow = A + (long)(rowBase + am) * K;
    // B loader: k = tid>>4, n4 = (tid&15)*4
    int bk = tid >> 4;
    int bn = (tid & 15) * 4;

    float4 sa, sb;

#define LOADG64(k0)                                                     \
    {                                                                   \
        sa = *(const float4*)(Arow + (k0) + ak);                        \
        sb = *(const float4*)(B + (long)((k0) + bk) * N + colBase + bn);\
    }
#define STS64(bufi)                                                     \
    {                                                                   \
        As[bufi][ak + 0][am] = sa.x;                                    \
        As[bufi][ak + 1][am] = sa.y;                                    \
        As[bufi][ak + 2][am] = sa.z;                                    \
        As[bufi][ak + 3][am] = sa.w;                                    \
        *(float4*)&Bs[bufi][bk][bn] = sb;                               \
    }

    LOADG64(0);
    STS64(0);
    __syncthreads();

    int buf = 0;
    for (int k0 = 0; k0 < K; k0 += BK) {
        bool has_next = (k0 + BK) < K;
        if (has_next) LOADG64(k0 + BK);

#pragma unroll
        for (int kk = 0; kk < BK; kk++) {
            float4 a4 = *(const float4*)&As[buf][kk][tr * 4];
            float4 b4 = *(const float4*)&Bs[buf][kk][tc * 4];
            float a[4] = {a4.x, a4.y, a4.z, a4.w};
            float b[4] = {b4.x, b4.y, b4.z, b4.w};
#pragma unroll
            for (int i = 0; i < 4; i++)
#pragma unroll
                for (int j = 0; j < 4; j++) acc[i][j] = fmaf(a[i], b[j], acc[i][j]);
        }

        if (has_next) STS64(buf ^ 1);
        __syncthreads();
        buf ^= 1;
    }

#pragma unroll
    for (int i = 0; i < 4; i++) {
        int row = rowBase + tr * 4 + i;
#pragma unroll
        for (int j = 0; j < 4; j++) {
            int col = colBase + tc * 4 + j;
            if (MODE == 0) Cmat[(long)row * N + col] = acc[i][j];
            else           Cmat[(long)row * N + col] += acc[i][j];
        }
    }
#undef LOADG64
#undef STS64
}

// ---------------- small kernels ----------------
__global__ void embed_kernel(const int* __restrict__ ids, const float* __restrict__ emb,
                             float* __restrict__ hs) {
    int t = blockIdx.x, c = threadIdx.x;
    hs[t * C_ + c] = emb[(size_t)ids[t] * C_ + c];
}

__global__ void layernorm_k(const float* __restrict__ in, const float* __restrict__ w,
                            const float* __restrict__ b, float* __restrict__ out) {
    int t = blockIdx.x, c = threadIdx.x;
    __shared__ float red[256];
    float x = in[t * C_ + c];
    red[c] = x;
    __syncthreads();
    for (int s = 128; s > 0; s >>= 1) { if (c < s) red[c] += red[c + s]; __syncthreads(); }
    float mu = red[0] * (1.0f / C_);
    __syncthreads();
    float d = x - mu;
    red[c] = d * d;
    __syncthreads();
    for (int s = 128; s > 0; s >>= 1) { if (c < s) red[c] += red[c + s]; __syncthreads(); }
    float var = red[0] * (1.0f / C_);
    out[t * C_ + c] = d * rsqrtf(var + 1e-5f) * w[c] + b[c];
}

__global__ void attn_scores(const float* __restrict__ q, const float* __restrict__ k,
                            float* __restrict__ attn) {
    int bh = blockIdx.z;
    int qt = blockIdx.y * 32, kt = blockIdx.x * 32;
    if (kt > qt + 31) return;     // strictly-upper tile: never read downstream
    int b = bh / H_, h = bh % H_;
    int ty = threadIdx.y, tx = threadIdx.x;
    int qi = qt + ty, ki = kt + tx;
    size_t oidx = ((size_t)bh * T_ + qi) * T_ + ki;
    __shared__ float qs[32][33], ks[32][33];
    qs[ty][tx] = q[(size_t)(b * T_ + qt + ty) * C_ + h * D_ + tx];
    ks[ty][tx] = k[(size_t)(b * T_ + kt + ty) * C_ + h * D_ + tx];
    __syncthreads();
    float s;
    if (ki <= qi) {
        float a = 0.0f;
#pragma unroll
        for (int d = 0; d < 32; d++) a = fmaf(qs[ty][d], ks[tx][d], a);
        s = a * 0.17677669529663687f;
    } else {
        s = -1e30f;
    }
    attn[oidx] = s;
}

// causal softmax: row `t` only has valid entries k <= t; untouched entries never read
__global__ void softmax_causal(float* __restrict__ attn) {
    size_t rowg = blockIdx.x;
    int row = (int)(rowg & (T_ - 1));
    int len = row + 1;
    float* p = attn + rowg * (size_t)T_;
    int c = threadIdx.x;
    __shared__ float red[256];
    float v[4];
    float m = -INFINITY;
#pragma unroll
    for (int i = 0; i < 4; i++) {
        int idx = c + 256 * i;
        v[i] = (idx < len) ? p[idx] : -INFINITY;
        m = fmaxf(m, v[i]);
    }
    red[c] = m;
    __syncthreads();
    for (int s = 128; s > 0; s >>= 1) { if (c < s) red[c] = fmaxf(red[c], red[c + s]); __syncthreads(); }
    m = red[0];
    __syncthreads();
    float s = 0.0f;
#pragma unroll
    for (int i = 0; i < 4; i++) { v[i] = expf(v[i] - m); s += v[i]; }   // exp(-inf)=0
    red[c] = s;
    __syncthreads();
    for (int st = 128; st > 0; st >>= 1) { if (c < st) red[c] += red[c + st]; __syncthreads(); }
    float inv = 1.0f / red[0];
#pragma unroll
    for (int i = 0; i < 4; i++) {
        int idx = c + 256 * i;
        if (idx < len) p[idx] = v[i] * inv;
    }
}

__global__ void attn_av(const float* __restrict__ attn, const float* __restrict__ v,
                        float* __restrict__ ao) {
    int bh = blockIdx.y;
    int b = bh / H_, h = bh % H_;
    int d = threadIdx.x % 32;
    int qi = threadIdx.x / 32;
    int q = blockIdx.x * 8 + qi;
    const float* arow = attn + ((size_t)bh * T_ + q) * T_;
    float acc = 0.0f;
#pragma unroll 4
    for (int k = 0; k <= q; k++)
        acc = fmaf(arow[k], v[(size_t)(b * T_ + k) * C_ + h * D_ + d], acc);
    ao[(size_t)(b * T_ + q) * C_ + h * D_ + d] = acc;
}

__global__ void snorm_kernel(const float* __restrict__ sim, float* __restrict__ snorm) {
    int e = threadIdx.x;
    float ss = 0.0f;
    for (int c = 0; c < C_; c++) { float v = sim[c * E_ + e]; ss += v * v; }
    snorm[e] = sqrtf(ss);
}

__global__ void gating_kernel(const float* __restrict__ xt, const float* __restrict__ sim,
                              const float* __restrict__ gates, const float* __restrict__ snorm,
                              float* __restrict__ pre_out, float* __restrict__ amask_out,
                              float* __restrict__ rw) {
    int t = blockIdx.x;
    int lane = threadIdx.x;
    const unsigned FULL = 0xffffffffu;

    float ss = 0.0f;
#pragma unroll
    for (int i = 0; i < 8; i++) { float v = xt[t * C_ + lane + i * 32]; ss += v * v; }
#pragma unroll
    for (int o = 16; o; o >>= 1) ss += __shfl_xor_sync(FULL, ss, o);
    float xnorm = fmaxf(sqrtf(ss), 1e-12f);

    float dot = 0.0f;
    for (int c = 0; c < C_; c++) dot = fmaf(xt[t * C_ + c], sim[c * E_ + lane], dot);
    float logit = dot / (xnorm * fmaxf(snorm[lane], 1e-12f));

    float sig = 1.0f / (1.0f + expf(-gates[lane]));
    float pre = logit - sig;
    pre_out[t * E_ + lane] = pre;

    float gated = fmaxf(pre, 0.0f);
    bool active = pre > 0.0f;
    unsigned bal = __ballot_sync(FULL, active);
    bool sel;
    if (bal == 0u) {
        int rank = 0;
        float my = logit;
#pragma unroll
        for (int j = 0; j < 32; j++) {
            float lj = __shfl_sync(FULL, my, j);
            if (lj > my || (lj == my && j < lane)) rank++;
        }
        sel = rank < (E_ / 2);
    } else {
        sel = active;
    }
    amask_out[t * E_ + lane] = sel ? 1.0f : 0.0f;

    const float NEGV = -3.3895313892515355e38f;
    float gl = sel ? gated : NEGV;
    float m = gl;
#pragma unroll
    for (int o = 16; o; o >>= 1) m = fmaxf(m, __shfl_xor_sync(FULL, m, o));
    float ex = expf(gl - m);
    float s = ex;
#pragma unroll
    for (int o = 16; o; o >>= 1) s += __shfl_xor_sync(FULL, s, o);
    rw[t * E_ + lane] = ex / s;
}

// deterministic per-expert token compaction (1 warp per expert)
__global__ void build_lists(const float* __restrict__ mask, int* __restrict__ counts,
                            int* __restrict__ lists) {
    int e = blockIdx.x;
    int lane = threadIdx.x;
    int cnt = 0;
    for (int base = 0; base < N_; base += 32) {
        int t = base + lane;
        bool a = mask[t * E_ + e] > 0.5f;
        unsigned bal = __ballot_sync(0xffffffffu, a);
        int pos = cnt + __popc(bal & ((1u << lane) - 1u));
        if (a) lists[e * N_ + pos] = t;
        cnt += __popc(bal);
    }
    if (lane == 0) counts[e] = cnt;
}

__global__ void zero_feo(float4* __restrict__ p) {
    size_t i = (size_t)blockIdx.x * blockDim.x + threadIdx.x;
    p[i] = make_float4(0.f, 0.f, 0.f, 0.f);
}

__global__ void moe_reduce(const float* __restrict__ rw, const float* __restrict__ feo,
                           float* __restrict__ hs) {
    int t = blockIdx.x, c = threadIdx.x;
    float acc = 0.0f;
#pragma unroll
    for (int e = 0; e < E_; e++)
        acc = fmaf(rw[t * E_ + e], feo[((size_t)t * E_ + e) * C_ + c], acc);
    hs[t * C_ + c] += acc;
}

// ---------------- launcher ----------------
extern "C" void kernel_launch(void* const* d_in, const int* in_sizes, int n_in,
                              void* d_out, int out_size) {
    const int*   ids   = (const int*)d_in[0];
    const float* emb   = (const float*)d_in[1];
    const float* wq    = (const float*)d_in[2];
    const float* wk    = (const float*)d_in[3];
    const float* wv    = (const float*)d_in[4];
    const float* wo    = (const float*)d_in[5];
    const float* ln1w  = (const float*)d_in[6];
    const float* ln1b  = (const float*)d_in[7];
    const float* ln2w  = (const float*)d_in[8];
    const float* ln2b  = (const float*)d_in[9];
    const float* sim   = (const float*)d_in[10];
    const float* gates = (const float*)d_in[11];
    const float* w1    = (const float*)d_in[12];
    const float* w2    = (const float*)d_in[13];
    const float* lmh   = (const float*)d_in[14];

    float* out = (float*)d_out;
    float* out_logits = out;
    float* out_feo    = out_logits + (size_t)B_ * T_ * V_;
    float* out_pre    = out_feo + (size_t)N_ * E_ * C_;
    float* out_mask   = out_pre + (size_t)N_ * E_;

    float *hs, *ln, *qb, *kb, *vb, *ao, *attn, *Hbuf, *rw, *snorm;
    int *counts, *lists;
    cudaGetSymbolAddress((void**)&hs, g_hs);
    cudaGetSymbolAddress((void**)&ln, g_ln);
    cudaGetSymbolAddress((void**)&qb, g_q);
    cudaGetSymbolAddress((void**)&kb, g_k);
    cudaGetSymbolAddress((void**)&vb, g_v);
    cudaGetSymbolAddress((void**)&ao, g_ao);
    cudaGetSymbolAddress((void**)&attn, g_attn);
    cudaGetSymbolAddress((void**)&Hbuf, g_Hbuf);
    cudaGetSymbolAddress((void**)&rw, g_rw);
    cudaGetSymbolAddress((void**)&snorm, g_snorm);
    cudaGetSymbolAddress((void**)&counts, g_counts);
    cudaGetSymbolAddress((void**)&lists, g_lists);

    snorm_kernel<<<1, 32>>>(sim, snorm);
    embed_kernel<<<N_, 256>>>(ids, emb, hs);
    layernorm_k<<<N_, 256>>>(hs, ln1w, ln1b, ln);

    // Q/K/V projections (fp32, 64x64 tiles -> 128 blocks each)
    dim3 g64(C_ / 64, N_ / 64);
    sgemm64<0><<<g64, 256>>>(ln, wq, qb, C_, C_);
    sgemm64<0><<<g64, 256>>>(ln, wk, kb, C_, C_);
    sgemm64<0><<<g64, 256>>>(ln, wv, vb, C_, C_);

    attn_scores<<<dim3(32, 32, B_ * H_), dim3(32, 32)>>>(qb, kb, attn);
    softmax_causal<<<B_ * H_ * T_, 256>>>(attn);
    attn_av<<<dim3(T_ / 8, B_ * H_), 256>>>(attn, vb, ao);

    sgemm64<4><<<g64, 256>>>(ao, wo, hs, C_, C_);   // hs += ao@wo

    layernorm_k<<<N_, 256>>>(hs, ln2w, ln2b, ln);
    gating_kernel<<<N_, 32>>>(ln, sim, gates, snorm, out_pre, out_mask, rw);
    build_lists<<<E_, 32>>>(out_mask, counts, lists);

    // zero full_expert_outputs (inactive pairs must be exactly 0)
    zero_feo<<<(N_ * E_ * C_ / 4) / 256, 256>>>((float4*)out_feo);

    // sparse MoE up: gather active tokens per expert, gelu, compact H
    gemm_tf32<1><<<dim3(F_ / 128, N_ / 128, E_), 256>>>(
        ln, w1, Hbuf, 0, F_, C_, (long)C_ * F_, (long)N_ * F_, lists, counts);
    // sparse MoE down: compact H -> scatter into feo
    gemm_tf32<2><<<dim3(C_ / 128, N_ / 128, E_), 256>>>(
        Hbuf, w2, out_feo, 0, C_, F_, (long)F_ * C_, (long)N_ * F_, lists, counts);

    moe_reduce<<<N_, 256>>>(rw, out_feo, hs);

    // LM head (tf32): [2048,256] @ [256,50257]
    gemm_tf32<0><<<dim3((V_ + 127) / 128, N_ / 128, 1), 256>>>(
        hs, lmh, out_logits, N_, V_, C_, 0, 0, nullptr, nullptr);
}

// round 9
// speedup vs baseline: 3.1901x; 1.0294x over previous
#include <cuda_runtime.h>
#include <cuda_bf16.h>
#include <math.h>

#define B_ 2
#define T_ 1024
#define C_ 256
#define F_ 1024
#define E_ 32
#define V_ 50257
#define H_ 8
#define D_ 32
#define N_ 2048
#define VP_ 50304            // V padded to multiple of 128

// ---------------- scratch (static device globals; no allocations) ----------------
__device__ float g_hs[N_ * C_];
__device__ float g_ln[N_ * C_];
__device__ float g_q[N_ * C_];
__device__ float g_k[N_ * C_];
__device__ float g_v[N_ * C_];
__device__ float g_ao[N_ * C_];
__device__ float g_attn[(size_t)B_ * H_ * T_ * T_];
__device__ float g_Hbuf[(size_t)E_ * N_ * F_];      // compact gelu(H), tf32-rounded
__device__ float g_rw[N_ * E_];
__device__ float g_snorm[E_];
__device__ int   g_counts[E_];
__device__ int   g_lists[E_ * N_];
// tf32-pre-rounded operand copies
__device__ float g_w1r[(size_t)E_ * C_ * F_];
__device__ float g_w2r[(size_t)E_ * F_ * C_];
__device__ float g_lmhr[(size_t)C_ * VP_];
__device__ float g_lnr[N_ * C_];
__device__ float g_hsr[N_ * C_];

__device__ __forceinline__ float gelu_f(float x) {
    return 0.5f * x * (1.0f + erff(x * 0.70710678118654752440f));
}
__device__ __forceinline__ unsigned f2tf32(float x) {
    unsigned r;
    asm("cvt.rna.tf32.f32 %0, %1;" : "=r"(r) : "f"(x));
    return r;
}
__device__ __forceinline__ float tf32r(float x) { return __uint_as_float(f2tf32(x)); }

__device__ __forceinline__ void cpasync16(void* smem, const void* gmem) {
    unsigned saddr = (unsigned)__cvta_generic_to_shared(smem);
    asm volatile("cp.async.cg.shared.global [%0], [%1], 16;\n" :: "r"(saddr), "l"(gmem));
}
__device__ __forceinline__ void cp_commit() { asm volatile("cp.async.commit_group;\n"); }
template <int NN>
__device__ __forceinline__ void cp_wait() { asm volatile("cp.async.wait_group %0;\n" :: "n"(NN)); }

// ============ tf32 GEMM: 128 threads, 4 warps x (64x64), BK=16, cp.async 2-stage =====
// All operands are PRE-ROUNDED to tf32 (RNA); HMMA truncation is then exact.
// MODE 0: dense C[M,Nout] = A @ B   (LM head; B = padded g_lmhr, ldb = VP_)
// MODE 1: sparse up: A rows gathered via lists[e]; C = tf32(gelu(acc)) -> compact Hbuf
// MODE 2: sparse down: A = compact Hbuf rows; C scattered to feo[t][e][:]
template <int MODE>
__global__ __launch_bounds__(128) void gemm_tf32p(
    const float* __restrict__ A, const float* __restrict__ Bg, float* __restrict__ Cg,
    int ldb, int Nout, int K, long strideB, long strideH,
    const int* __restrict__ lists, const int* __restrict__ counts)
{
    const int BK = 16;
    int e = blockIdx.z;
    int Me = (MODE == 0) ? N_ : counts[e];
    int rowBase = blockIdx.y * 128;
    if (MODE != 0 && rowBase >= Me) return;
    int colBase = blockIdx.x * 128;

    const float* Bp = (MODE == 0) ? Bg : (Bg + (long)e * strideB);
    const float* Ap = (MODE == 2) ? (A + (long)e * strideH) : A;

    __shared__ float As[2][128][20];   // [m][k], stride 20 -> conflict-free frags
    __shared__ float Bs[2][16][136];   // [k][n], stride 136 -> conflict-free frags

    int tid = threadIdx.x;
    int lane = tid & 31;
    int warp = tid >> 5;
    int m0 = (warp >> 1) * 64;     // warp grid 2x2
    int n0w = (warp & 1) * 64;
    int g = lane >> 2;             // 0..7
    int tg = lane & 3;             // 0..3

    float acc[4][8][4];
#pragma unroll
    for (int i = 0; i < 4; i++)
#pragma unroll
        for (int j = 0; j < 8; j++)
#pragma unroll
            for (int c = 0; c < 4; c++) acc[i][j][c] = 0.0f;

    // A loader: thread = row; 4x cp.async(16B) covers k0..k0+15
    int am = tid;
    int arow;
    if (MODE == 1) {
        int i = rowBase + am;
        arow = (i < Me) ? lists[e * N_ + i] : 0;
    } else {
        arow = rowBase + am;
    }
    const float* Arow = Ap + (long)arow * K;
    // B loader: bk = tid>>5 (0..3), bn = (tid&31)*4; 4 rows per thread
    int bk = tid >> 5;
    int bn = (lane) * 4;

#define LOADG(k0, bufi)                                                      \
    {                                                                        \
        cpasync16(&As[bufi][am][0],  Arow + (k0) + 0);                       \
        cpasync16(&As[bufi][am][4],  Arow + (k0) + 4);                       \
        cpasync16(&As[bufi][am][8],  Arow + (k0) + 8);                       \
        cpasync16(&As[bufi][am][12], Arow + (k0) + 12);                      \
        cpasync16(&Bs[bufi][bk +  0][bn], Bp + (long)((k0) + bk +  0) * ldb + colBase + bn); \
        cpasync16(&Bs[bufi][bk +  4][bn], Bp + (long)((k0) + bk +  4) * ldb + colBase + bn); \
        cpasync16(&Bs[bufi][bk +  8][bn], Bp + (long)((k0) + bk +  8) * ldb + colBase + bn); \
        cpasync16(&Bs[bufi][bk + 12][bn], Bp + (long)((k0) + bk + 12) * ldb + colBase + bn); \
        cp_commit();                                                         \
    }

    LOADG(0, 0);
    int buf = 0;
    for (int k0 = 0; k0 < K; k0 += BK) {
        bool has_next = (k0 + BK) < K;
        if (has_next) { LOADG(k0 + BK, buf ^ 1); cp_wait<1>(); }
        else          { cp_wait<0>(); }
        __syncthreads();

#pragma unroll
        for (int ks = 0; ks < BK; ks += 8) {
            unsigned af[4][4];
#pragma unroll
            for (int mi = 0; mi < 4; mi++) {
                int r = m0 + mi * 16 + g;
                af[mi][0] = __float_as_uint(As[buf][r][ks + tg]);
                af[mi][1] = __float_as_uint(As[buf][r + 8][ks + tg]);
                af[mi][2] = __float_as_uint(As[buf][r][ks + tg + 4]);
                af[mi][3] = __float_as_uint(As[buf][r + 8][ks + tg + 4]);
            }
            unsigned bf[8][2];
#pragma unroll
            for (int ni = 0; ni < 8; ni++) {
                int c = n0w + ni * 8 + g;
                bf[ni][0] = __float_as_uint(Bs[buf][ks + tg][c]);
                bf[ni][1] = __float_as_uint(Bs[buf][ks + tg + 4][c]);
            }
#pragma unroll
            for (int mi = 0; mi < 4; mi++)
#pragma unroll
                for (int ni = 0; ni < 8; ni++) {
                    asm volatile(
                        "mma.sync.aligned.m16n8k8.row.col.f32.tf32.tf32.f32 "
                        "{%0,%1,%2,%3}, {%4,%5,%6,%7}, {%8,%9}, {%0,%1,%2,%3};\n"
                        : "+f"(acc[mi][ni][0]), "+f"(acc[mi][ni][1]),
                          "+f"(acc[mi][ni][2]), "+f"(acc[mi][ni][3])
                        : "r"(af[mi][0]), "r"(af[mi][1]), "r"(af[mi][2]), "r"(af[mi][3]),
                          "r"(bf[ni][0]), "r"(bf[ni][1]));
                }
        }
        __syncthreads();   // protect stage about to be overwritten next iter
        buf ^= 1;
    }

    // epilogue
#pragma unroll
    for (int mi = 0; mi < 4; mi++) {
#pragma unroll
        for (int half = 0; half < 2; half++) {
            int i = rowBase + m0 + mi * 16 + g + half * 8;
#pragma unroll
            for (int ni = 0; ni < 8; ni++) {
                float c0 = acc[mi][ni][half * 2 + 0];
                float c1 = acc[mi][ni][half * 2 + 1];
                int col = colBase + n0w + ni * 8 + 2 * tg;
                if (MODE == 0) {
                    if (col < Nout)     Cg[(long)i * Nout + col] = c0;
                    if (col + 1 < Nout) Cg[(long)i * Nout + col + 1] = c1;
                } else if (MODE == 1) {
                    if (i < Me) {
                        float* dst = Cg + (long)e * strideH + (long)i * F_ + col;
                        dst[0] = tf32r(gelu_f(c0));
                        dst[1] = tf32r(gelu_f(c1));
                    }
                } else {
                    if (i < Me) {
                        int t = lists[e * N_ + i];
                        float* dst = Cg + ((long)t * E_ + e) * C_ + col;
                        dst[0] = c0;
                        dst[1] = c1;
                    }
                }
            }
        }
    }
#undef LOADG
}

// ============ fp32 SGEMM 64x64 (attention path, precision-critical) ==================
// MODE 0: C = acc; MODE 4: C += acc; QKV: fused z-variant below.
template <int MODE>
__global__ __launch_bounds__(256) void sgemm64(
    const float* __restrict__ A, const float* __restrict__ B, float* __restrict__ Cmat,
    int N, int K)
{
    const int BM = 64, BN = 64, BK = 16;
    __shared__ float As[2][BK][BM + 4];
    __shared__ float Bs[2][BK][BN + 4];

    int tid = threadIdx.x;
    int rowBase = blockIdx.y * BM;
    int colBase = blockIdx.x * BN;
    int tr = tid >> 4, tc = tid & 15;

    float acc[4][4];
#pragma unroll
    for (int i = 0; i < 4; i++)
#pragma unroll
        for (int j = 0; j < 4; j++) acc[i][j] = 0.0f;

    int am = tid & 63;
    int ak = (tid >> 6) * 4;
    const float* Arow = A + (long)(rowBase + am) * K;
    int bk = tid >> 4;
    int bn = (tid & 15) * 4;

    float4 sa, sb;
#define LOADG64(k0)                                                     \
    {                                                                   \
        sa = *(const float4*)(Arow + (k0) + ak);                        \
        sb = *(const float4*)(B + (long)((k0) + bk) * N + colBase + bn);\
    }
#define STS64(bufi)                                                     \
    {                                                                   \
        As[bufi][ak + 0][am] = sa.x;                                    \
        As[bufi][ak + 1][am] = sa.y;                                    \
        As[bufi][ak + 2][am] = sa.z;                                    \
        As[bufi][ak + 3][am] = sa.w;                                    \
        *(float4*)&Bs[bufi][bk][bn] = sb;                               \
    }
    LOADG64(0); STS64(0);
    __syncthreads();
    int buf = 0;
    for (int k0 = 0; k0 < K; k0 += BK) {
        bool has_next = (k0 + BK) < K;
        if (has_next) LOADG64(k0 + BK);
#pragma unroll
        for (int kk = 0; kk < BK; kk++) {
            float4 a4 = *(const float4*)&As[buf][kk][tr * 4];
            float4 b4 = *(const float4*)&Bs[buf][kk][tc * 4];
            float a[4] = {a4.x, a4.y, a4.z, a4.w};
            float b[4] = {b4.x, b4.y, b4.z, b4.w};
#pragma unroll
            for (int i = 0; i < 4; i++)
#pragma unroll
                for (int j = 0; j < 4; j++) acc[i][j] = fmaf(a[i], b[j], acc[i][j]);
        }
        if (has_next) STS64(buf ^ 1);
        __syncthreads();
        buf ^= 1;
    }
#pragma unroll
    for (int i = 0; i < 4; i++) {
        int row = rowBase + tr * 4 + i;
#pragma unroll
        for (int j = 0; j < 4; j++) {
            int col = colBase + tc * 4 + j;
            if (MODE == 0) Cmat[(long)row * N + col] = acc[i][j];
            else           Cmat[(long)row * N + col] += acc[i][j];
        }
    }
#undef LOADG64
#undef STS64
}

// fused QKV: blockIdx.z selects weight/output; N=K=256
__global__ __launch_bounds__(256) void sgemm64_qkv(
    const float* __restrict__ A,
    const float* __restrict__ Wq, const float* __restrict__ Wk, const float* __restrict__ Wv,
    float* __restrict__ Oq, float* __restrict__ Ok, float* __restrict__ Ov)
{
    const int BM = 64, BN = 64, BK = 16, N = 256, K = 256;
    int z = blockIdx.z;
    const float* B = (z == 0) ? Wq : (z == 1) ? Wk : Wv;
    float* Cmat = (z == 0) ? Oq : (z == 1) ? Ok : Ov;

    __shared__ float As[2][BK][BM + 4];
    __shared__ float Bs[2][BK][BN + 4];

    int tid = threadIdx.x;
    int rowBase = blockIdx.y * BM;
    int colBase = blockIdx.x * BN;
    int tr = tid >> 4, tc = tid & 15;

    float acc[4][4];
#pragma unroll
    for (int i = 0; i < 4; i++)
#pragma unroll
        for (int j = 0; j < 4; j++) acc[i][j] = 0.0f;

    int am = tid & 63;
    int ak = (tid >> 6) * 4;
    const float* Arow = A + (long)(rowBase + am) * K;
    int bk = tid >> 4;
    int bn = (tid & 15) * 4;

    float4 sa, sb;
#define LOADG64(k0)                                                     \
    {                                                                   \
        sa = *(const float4*)(Arow + (k0) + ak);                        \
        sb = *(const float4*)(B + (long)((k0) + bk) * N + colBase + bn);\
    }
#define STS64(bufi)                                                     \
    {                                                                   \
        As[bufi][ak + 0][am] = sa.x;                                    \
        As[bufi][ak + 1][am] = sa.y;                                    \
        As[bufi][ak + 2][am] = sa.z;                                    \
        As[bufi][ak + 3][am] = sa.w;                                    \
        *(float4*)&Bs[bufi][bk][bn] = sb;                               \
    }
    LOADG64(0); STS64(0);
    __syncthreads();
    int buf = 0;
    for (int k0 = 0; k0 < K; k0 += BK) {
        bool has_next = (k0 + BK) < K;
        if (has_next) LOADG64(k0 + BK);
#pragma unroll
        for (int kk = 0; kk < BK; kk++) {
            float4 a4 = *(const float4*)&As[buf][kk][tr * 4];
            float4 b4 = *(const float4*)&Bs[buf][kk][tc * 4];
            float a[4] = {a4.x, a4.y, a4.z, a4.w};
            float b[4] = {b4.x, b4.y, b4.z, b4.w};
#pragma unroll
            for (int i = 0; i < 4; i++)
#pragma unroll
                for (int j = 0; j < 4; j++) acc[i][j] = fmaf(a[i], b[j], acc[i][j]);
        }
        if (has_next) STS64(buf ^ 1);
        __syncthreads();
        buf ^= 1;
    }
#pragma unroll
    for (int i = 0; i < 4; i++) {
        int row = rowBase + tr * 4 + i;
#pragma unroll
        for (int j = 0; j < 4; j++)
            Cmat[(long)row * N + colBase + tc * 4 + j] = acc[i][j];
    }
#undef LOADG64
#undef STS64
}

// ---------------- prepass rounding kernels ----------------
__global__ void round4_kernel(const float4* __restrict__ src, float4* __restrict__ dst) {
    size_t i = (size_t)blockIdx.x * blockDim.x + threadIdx.x;
    float4 v = src[i];
    v.x = tf32r(v.x); v.y = tf32r(v.y); v.z = tf32r(v.z); v.w = tf32r(v.w);
    dst[i] = v;
}
// lm_head [C, V] -> padded rounded [C, VP_]
__global__ void round_pad_lmh(const float* __restrict__ src, float* __restrict__ dst) {
    int c = blockIdx.x * 128 + threadIdx.x;
    int r = blockIdx.y;
    dst[(long)r * VP_ + c] = (c < V_) ? tf32r(src[(long)r * V_ + c]) : 0.0f;
}

// ---------------- small kernels ----------------
__global__ void embed_kernel(const int* __restrict__ ids, const float* __restrict__ emb,
                             float* __restrict__ hs) {
    int t = blockIdx.x, c = threadIdx.x;
    hs[t * C_ + c] = emb[(size_t)ids[t] * C_ + c];
}

__global__ void layernorm_k(const float* __restrict__ in, const float* __restrict__ w,
                            const float* __restrict__ b, float* __restrict__ out) {
    int t = blockIdx.x, c = threadIdx.x;
    __shared__ float red[256];
    float x = in[t * C_ + c];
    red[c] = x;
    __syncthreads();
    for (int s = 128; s > 0; s >>= 1) { if (c < s) red[c] += red[c + s]; __syncthreads(); }
    float mu = red[0] * (1.0f / C_);
    __syncthreads();
    float d = x - mu;
    red[c] = d * d;
    __syncthreads();
    for (int s = 128; s > 0; s >>= 1) { if (c < s) red[c] += red[c + s]; __syncthreads(); }
    float var = red[0] * (1.0f / C_);
    out[t * C_ + c] = d * rsqrtf(var + 1e-5f) * w[c] + b[c];
}

__global__ void attn_scores(const float* __restrict__ q, const float* __restrict__ k,
                            float* __restrict__ attn) {
    int bh = blockIdx.z;
    int qt = blockIdx.y * 32, kt = blockIdx.x * 32;
    if (kt > qt + 31) return;
    int b = bh / H_, h = bh % H_;
    int ty = threadIdx.y, tx = threadIdx.x;
    int qi = qt + ty, ki = kt + tx;
    size_t oidx = ((size_t)bh * T_ + qi) * T_ + ki;
    __shared__ float qs[32][33], ks[32][33];
    qs[ty][tx] = q[(size_t)(b * T_ + qt + ty) * C_ + h * D_ + tx];
    ks[ty][tx] = k[(size_t)(b * T_ + kt + ty) * C_ + h * D_ + tx];
    __syncthreads();
    float s;
    if (ki <= qi) {
        float a = 0.0f;
#pragma unroll
        for (int d = 0; d < 32; d++) a = fmaf(qs[ty][d], ks[tx][d], a);
        s = a * 0.17677669529663687f;
    } else {
        s = -1e30f;
    }
    attn[oidx] = s;
}

__global__ void softmax_causal(float* __restrict__ attn) {
    size_t rowg = blockIdx.x;
    int row = (int)(rowg & (T_ - 1));
    int len = row + 1;
    float* p = attn + rowg * (size_t)T_;
    int c = threadIdx.x;
    __shared__ float red[256];
    float v[4];
    float m = -INFINITY;
#pragma unroll
    for (int i = 0; i < 4; i++) {
        int idx = c + 256 * i;
        v[i] = (idx < len) ? p[idx] : -INFINITY;
        m = fmaxf(m, v[i]);
    }
    red[c] = m;
    __syncthreads();
    for (int s = 128; s > 0; s >>= 1) { if (c < s) red[c] = fmaxf(red[c], red[c + s]); __syncthreads(); }
    m = red[0];
    __syncthreads();
    float s = 0.0f;
#pragma unroll
    for (int i = 0; i < 4; i++) { v[i] = expf(v[i] - m); s += v[i]; }
    red[c] = s;
    __syncthreads();
    for (int st = 128; st > 0; st >>= 1) { if (c < st) red[c] += red[c + st]; __syncthreads(); }
    float inv = 1.0f / red[0];
#pragma unroll
    for (int i = 0; i < 4; i++) {
        int idx = c + 256 * i;
        if (idx < len) p[idx] = v[i] * inv;
    }
}

__global__ void attn_av(const float* __restrict__ attn, const float* __restrict__ v,
                        float* __restrict__ ao) {
    int bh = blockIdx.y;
    int b = bh / H_, h = bh % H_;
    int d = threadIdx.x % 32;
    int qi = threadIdx.x / 32;
    int q = blockIdx.x * 8 + qi;
    const float* arow = attn + ((size_t)bh * T_ + q) * T_;
    const float* vbase = v + (size_t)b * T_ * C_ + h * D_ + d;
    float a0 = 0.f, a1 = 0.f, a2 = 0.f, a3 = 0.f;
    int k = 0;
    for (; k + 3 <= q; k += 4) {
        a0 = fmaf(arow[k + 0], vbase[(size_t)(k + 0) * C_], a0);
        a1 = fmaf(arow[k + 1], vbase[(size_t)(k + 1) * C_], a1);
        a2 = fmaf(arow[k + 2], vbase[(size_t)(k + 2) * C_], a2);
        a3 = fmaf(arow[k + 3], vbase[(size_t)(k + 3) * C_], a3);
    }
    for (; k <= q; k++) a0 = fmaf(arow[k], vbase[(size_t)k * C_], a0);
    ao[(size_t)(b * T_ + q) * C_ + h * D_ + d] = (a0 + a1) + (a2 + a3);
}

__global__ void snorm_kernel(const float* __restrict__ sim, float* __restrict__ snorm) {
    int e = threadIdx.x;
    float ss = 0.0f;
    for (int c = 0; c < C_; c++) { float v = sim[c * E_ + e]; ss += v * v; }
    snorm[e] = sqrtf(ss);
}

__global__ void gating_kernel(const float* __restrict__ xt, const float* __restrict__ sim,
                              const float* __restrict__ gates, const float* __restrict__ snorm,
                              float* __restrict__ pre_out, float* __restrict__ amask_out,
                              float* __restrict__ rw) {
    int t = blockIdx.x;
    int lane = threadIdx.x;
    const unsigned FULL = 0xffffffffu;

    float ss = 0.0f;
#pragma unroll
    for (int i = 0; i < 8; i++) { float v = xt[t * C_ + lane + i * 32]; ss += v * v; }
#pragma unroll
    for (int o = 16; o; o >>= 1) ss += __shfl_xor_sync(FULL, ss, o);
    float xnorm = fmaxf(sqrtf(ss), 1e-12f);

    float dot = 0.0f;
    for (int c = 0; c < C_; c++) dot = fmaf(xt[t * C_ + c], sim[c * E_ + lane], dot);
    float logit = dot / (xnorm * fmaxf(snorm[lane], 1e-12f));

    float sig = 1.0f / (1.0f + expf(-gates[lane]));
    float pre = logit - sig;
    pre_out[t * E_ + lane] = pre;

    float gated = fmaxf(pre, 0.0f);
    bool active = pre > 0.0f;
    unsigned bal = __ballot_sync(FULL, active);
    bool sel;
    if (bal == 0u) {
        int rank = 0;
        float my = logit;
#pragma unroll
        for (int j = 0; j < 32; j++) {
            float lj = __shfl_sync(FULL, my, j);
            if (lj > my || (lj == my && j < lane)) rank++;
        }
        sel = rank < (E_ / 2);
    } else {
        sel = active;
    }
    amask_out[t * E_ + lane] = sel ? 1.0f : 0.0f;

    const float NEGV = -3.3895313892515355e38f;
    float gl = sel ? gated : NEGV;
    float m = gl;
#pragma unroll
    for (int o = 16; o; o >>= 1) m = fmaxf(m, __shfl_xor_sync(FULL, m, o));
    float ex = expf(gl - m);
    float s = ex;
#pragma unroll
    for (int o = 16; o; o >>= 1) s += __shfl_xor_sync(FULL, s, o);
    rw[t * E_ + lane] = ex / s;
}

__global__ void build_lists(const float* __restrict__ mask, int* __restrict__ counts,
                            int* __restrict__ lists) {
    int e = blockIdx.x;
    int lane = threadIdx.x;
    int cnt = 0;
    for (int base = 0; base < N_; base += 32) {
        int t = base + lane;
        bool a = mask[t * E_ + e] > 0.5f;
        unsigned bal = __ballot_sync(0xffffffffu, a);
        int pos = cnt + __popc(bal & ((1u << lane) - 1u));
        if (a) lists[e * N_ + pos] = t;
        cnt += __popc(bal);
    }
    if (lane == 0) counts[e] = cnt;
}

__global__ void zero_feo(float4* __restrict__ p) {
    size_t i = (size_t)blockIdx.x * blockDim.x + threadIdx.x;
    p[i] = make_float4(0.f, 0.f, 0.f, 0.f);
}

__global__ void moe_reduce(const float* __restrict__ rw, const float* __restrict__ feo,
                           float* __restrict__ hs) {
    int t = blockIdx.x, c = threadIdx.x;
    float acc = 0.0f;
#pragma unroll
    for (int e = 0; e < E_; e++)
        acc = fmaf(rw[t * E_ + e], feo[((size_t)t * E_ + e) * C_ + c], acc);
    hs[t * C_ + c] += acc;
}

// ---------------- launcher ----------------
extern "C" void kernel_launch(void* const* d_in, const int* in_sizes, int n_in,
                              void* d_out, int out_size) {
    const int*   ids   = (const int*)d_in[0];
    const float* emb   = (const float*)d_in[1];
    const float* wq    = (const float*)d_in[2];
    const float* wk    = (const float*)d_in[3];
    const float* wv    = (const float*)d_in[4];
    const float* wo    = (const float*)d_in[5];
    const float* ln1w  = (const float*)d_in[6];
    const float* ln1b  = (const float*)d_in[7];
    const float* ln2w  = (const float*)d_in[8];
    const float* ln2b  = (const float*)d_in[9];
    const float* sim   = (const float*)d_in[10];
    const float* gates = (const float*)d_in[11];
    const float* w1    = (const float*)d_in[12];
    const float* w2    = (const float*)d_in[13];
    const float* lmh   = (const float*)d_in[14];

    float* out = (float*)d_out;
    float* out_logits = out;
    float* out_feo    = out_logits + (size_t)B_ * T_ * V_;
    float* out_pre    = out_feo + (size_t)N_ * E_ * C_;
    float* out_mask   = out_pre + (size_t)N_ * E_;

    float *hs, *ln, *qb, *kb, *vb, *ao, *attn, *Hbuf, *rw, *snorm;
    float *w1r, *w2r, *lmhr, *lnr, *hsr;
    int *counts, *lists;
    cudaGetSymbolAddress((void**)&hs, g_hs);
    cudaGetSymbolAddress((void**)&ln, g_ln);
    cudaGetSymbolAddress((void**)&qb, g_q);
    cudaGetSymbolAddress((void**)&kb, g_k);
    cudaGetSymbolAddress((void**)&vb, g_v);
    cudaGetSymbolAddress((void**)&ao, g_ao);
    cudaGetSymbolAddress((void**)&attn, g_attn);
    cudaGetSymbolAddress((void**)&Hbuf, g_Hbuf);
    cudaGetSymbolAddress((void**)&rw, g_rw);
    cudaGetSymbolAddress((void**)&snorm, g_snorm);
    cudaGetSymbolAddress((void**)&counts, g_counts);
    cudaGetSymbolAddress((void**)&lists, g_lists);
    cudaGetSymbolAddress((void**)&w1r, g_w1r);
    cudaGetSymbolAddress((void**)&w2r, g_w2r);
    cudaGetSymbolAddress((void**)&lmhr, g_lmhr);
    cudaGetSymbolAddress((void**)&lnr, g_lnr);
    cudaGetSymbolAddress((void**)&hsr, g_hsr);

    // prepass: tf32-round weight operands into scratch
    round4_kernel<<<(E_ * C_ * F_ / 4) / 256, 256>>>((const float4*)w1, (float4*)w1r);
    round4_kernel<<<(E_ * F_ * C_ / 4) / 256, 256>>>((const float4*)w2, (float4*)w2r);
    round_pad_lmh<<<dim3(VP_ / 128, C_), 128>>>(lmh, lmhr);

    snorm_kernel<<<1, 32>>>(sim, snorm);
    embed_kernel<<<N_, 256>>>(ids, emb, hs);
    layernorm_k<<<N_, 256>>>(hs, ln1w, ln1b, ln);

    // fused QKV (fp32)
    sgemm64_qkv<<<dim3(C_ / 64, N_ / 64, 3), 256>>>(ln, wq, wk, wv, qb, kb, vb);

    attn_scores<<<dim3(32, 32, B_ * H_), dim3(32, 32)>>>(qb, kb, attn);
    softmax_causal<<<B_ * H_ * T_, 256>>>(attn);
    attn_av<<<dim3(T_ / 8, B_ * H_), 256>>>(attn, vb, ao);

    sgemm64<4><<<dim3(C_ / 64, N_ / 64), 256>>>(ao, wo, hs, C_, C_);   // hs += ao@wo

    layernorm_k<<<N_, 256>>>(hs, ln2w, ln2b, ln);
    round4_kernel<<<(N_ * C_ / 4) / 256, 256>>>((const float4*)ln, (float4*)lnr);
    gating_kernel<<<N_, 32>>>(ln, sim, gates, snorm, out_pre, out_mask, rw);
    build_lists<<<E_, 32>>>(out_mask, counts, lists);

    zero_feo<<<(N_ * E_ * C_ / 4) / 256, 256>>>((float4*)out_feo);

    // sparse MoE up: [cnt,256]@[256,1024] per expert, gelu, tf32-rounded compact H
    gemm_tf32p<1><<<dim3(F_ / 128, N_ / 128, E_), 128>>>(
        lnr, w1r, Hbuf, F_, F_, C_, (long)C_ * F_, (long)N_ * F_, lists, counts);
    // sparse MoE down: [cnt,1024]@[1024,256] -> scatter to feo
    gemm_tf32p<2><<<dim3(C_ / 128, N_ / 128, E_), 128>>>(
        Hbuf, w2r, out_feo, C_, C_, F_, (long)F_ * C_, (long)N_ * F_, lists, counts);

    moe_reduce<<<N_, 256>>>(rw, out_feo, hs);
    round4_kernel<<<(N_ * C_ / 4) / 256, 256>>>((const float4*)hs, (float4*)hsr);

    // LM head: [2048,256] @ [256,50304-padded] -> logits[:,:50257]
    gemm_tf32p<0><<<dim3(VP_ / 128, N_ / 128, 1), 128>>>(
        hsr, lmhr, out_logits, VP_, V_, C_, 0, 0, nullptr, nullptr);
}

// round 15
// speedup vs baseline: 3.2064x; 1.0051x over previous
#include <cuda_runtime.h>
#include <cuda_bf16.h>
#include <math.h>
#include <stdint.h>

#define B_ 2
#define T_ 1024
#define C_ 256
#define F_ 1024
#define E_ 32
#define V_ 50257
#define H_ 8
#define D_ 32
#define N_ 2048
#define VP_ 50304            // V padded to multiple of 128

// ---------------- scratch (static device globals; no allocations) ----------------
__device__ float g_hs[N_ * C_];
__device__ float g_ln[N_ * C_];
__device__ float g_q[N_ * C_];
__device__ float g_k[N_ * C_];
__device__ float g_v[N_ * C_];
__device__ float g_ao[N_ * C_];
__device__ float g_attn[(size_t)B_ * H_ * T_ * T_];
__device__ float g_Hbuf[(size_t)E_ * N_ * F_];      // compact gelu(H), tf32-rounded
__device__ float g_rw[N_ * E_];
__device__ float g_snorm[E_];
__device__ int   g_counts[E_];
__device__ int   g_lists[E_ * N_];
// tf32-pre-rounded operand copies
__device__ float g_w1r[(size_t)E_ * C_ * F_];
__device__ float g_w2r[(size_t)E_ * F_ * C_];
__device__ float g_lmhr[(size_t)C_ * VP_];          // lm_head padded [C, VP_], tf32-rounded
__device__ float g_lnr[N_ * C_];
__device__ float g_hsr[N_ * C_];

__device__ __forceinline__ float gelu_f(float x) {
    return 0.5f * x * (1.0f + erff(x * 0.70710678118654752440f));
}
__device__ __forceinline__ unsigned f2tf32(float x) {
    unsigned r;
    asm("cvt.rna.tf32.f32 %0, %1;" : "=r"(r) : "f"(x));
    return r;
}
__device__ __forceinline__ float tf32r(float x) { return __uint_as_float(f2tf32(x)); }

__device__ __forceinline__ void cpasync16(void* smem, const void* gmem) {
    unsigned saddr = (unsigned)__cvta_generic_to_shared(smem);
    asm volatile("cp.async.cg.shared.global [%0], [%1], 16;\n" :: "r"(saddr), "l"(gmem));
}
__device__ __forceinline__ void cp_commit() { asm volatile("cp.async.commit_group;\n"); }
template <int NN>
__device__ __forceinline__ void cp_wait() { asm volatile("cp.async.wait_group %0;\n" :: "n"(NN)); }

// ============ tf32 GEMM: 128 threads, 4 warps x (64x64), BK=16, cp.async 2-stage =====
// All operands PRE-ROUNDED to tf32 (RNA); HMMA truncation is then exact.
// MODE 0: dense C[M,Nout] = A @ B   (LM head; B = padded g_lmhr, ldb = VP_)
// MODE 1: sparse up: A rows gathered via lists[e]; C = tf32(gelu(acc)) -> compact Hbuf
// MODE 2: sparse down: A = compact Hbuf rows; C scattered to feo[t][e][:]
template <int MODE>
__global__ __launch_bounds__(128) void gemm_tf32p(
    const float* __restrict__ A, const float* __restrict__ Bg, float* __restrict__ Cg,
    int ldb, int Nout, int K, long strideB, long strideH,
    const int* __restrict__ lists, const int* __restrict__ counts)
{
    const int BK = 16;
    int e = blockIdx.z;
    int Me = (MODE == 0) ? N_ : counts[e];
    int rowBase = blockIdx.y * 128;
    if (MODE != 0 && rowBase >= Me) return;
    int colBase = blockIdx.x * 128;

    const float* Bp = (MODE == 0) ? Bg : (Bg + (long)e * strideB);
    const float* Ap = (MODE == 2) ? (A + (long)e * strideH) : A;

    __shared__ float As[2][128][20];   // [m][k], stride 20 -> conflict-free frags
    __shared__ float Bs[2][16][136];   // [k][n], stride 136 -> conflict-free frags

    int tid = threadIdx.x;
    int lane = tid & 31;
    int warp = tid >> 5;
    int m0 = (warp >> 1) * 64;     // warp grid 2x2
    int n0w = (warp & 1) * 64;
    int g = lane >> 2;             // 0..7
    int tg = lane & 3;             // 0..3

    float acc[4][8][4];
#pragma unroll
    for (int i = 0; i < 4; i++)
#pragma unroll
        for (int j = 0; j < 8; j++)
#pragma unroll
            for (int c = 0; c < 4; c++) acc[i][j][c] = 0.0f;

    // A loader: thread = row; 4x cp.async(16B) covers k0..k0+15
    int am = tid;
    int arow;
    if (MODE == 1) {
        int i = rowBase + am;
        arow = (i < Me) ? lists[e * N_ + i] : 0;
    } else {
        arow = rowBase + am;
    }
    const float* Arow = Ap + (long)arow * K;
    // B loader: bk = tid>>5 (0..3), bn = (tid&31)*4; 4 rows per thread
    int bk = tid >> 5;
    int bn = (lane) * 4;

#define LOADG(k0, bufi)                                                      \
    {                                                                        \
        cpasync16(&As[bufi][am][0],  Arow + (k0) + 0);                       \
        cpasync16(&As[bufi][am][4],  Arow + (k0) + 4);                       \
        cpasync16(&As[bufi][am][8],  Arow + (k0) + 8);                       \
        cpasync16(&As[bufi][am][12], Arow + (k0) + 12);                      \
        cpasync16(&Bs[bufi][bk +  0][bn], Bp + (long)((k0) + bk +  0) * ldb + colBase + bn); \
        cpasync16(&Bs[bufi][bk +  4][bn], Bp + (long)((k0) + bk +  4) * ldb + colBase + bn); \
        cpasync16(&Bs[bufi][bk +  8][bn], Bp + (long)((k0) + bk +  8) * ldb + colBase + bn); \
        cpasync16(&Bs[bufi][bk + 12][bn], Bp + (long)((k0) + bk + 12) * ldb + colBase + bn); \
        cp_commit();                                                         \
    }

    LOADG(0, 0);
    int buf = 0;
    for (int k0 = 0; k0 < K; k0 += BK) {
        bool has_next = (k0 + BK) < K;
        if (has_next) { LOADG(k0 + BK, buf ^ 1); cp_wait<1>(); }
        else          { cp_wait<0>(); }
        __syncthreads();

#pragma unroll
        for (int ks = 0; ks < BK; ks += 8) {
            unsigned af[4][4];
#pragma unroll
            for (int mi = 0; mi < 4; mi++) {
                int r = m0 + mi * 16 + g;
                af[mi][0] = __float_as_uint(As[buf][r][ks + tg]);
                af[mi][1] = __float_as_uint(As[buf][r + 8][ks + tg]);
                af[mi][2] = __float_as_uint(As[buf][r][ks + tg + 4]);
                af[mi][3] = __float_as_uint(As[buf][r + 8][ks + tg + 4]);
            }
            unsigned bf[8][2];
#pragma unroll
            for (int ni = 0; ni < 8; ni++) {
                int c = n0w + ni * 8 + g;
                bf[ni][0] = __float_as_uint(Bs[buf][ks + tg][c]);
                bf[ni][1] = __float_as_uint(Bs[buf][ks + tg + 4][c]);
            }
#pragma unroll
            for (int mi = 0; mi < 4; mi++)
#pragma unroll
                for (int ni = 0; ni < 8; ni++) {
                    asm volatile(
                        "mma.sync.aligned.m16n8k8.row.col.f32.tf32.tf32.f32 "
                        "{%0,%1,%2,%3}, {%4,%5,%6,%7}, {%8,%9}, {%0,%1,%2,%3};\n"
                        : "+f"(acc[mi][ni][0]), "+f"(acc[mi][ni][1]),
                          "+f"(acc[mi][ni][2]), "+f"(acc[mi][ni][3])
                        : "r"(af[mi][0]), "r"(af[mi][1]), "r"(af[mi][2]), "r"(af[mi][3]),
                          "r"(bf[ni][0]), "r"(bf[ni][1]));
                }
        }
        __syncthreads();   // protect stage about to be overwritten next iter
        buf ^= 1;
    }

    // epilogue
#pragma unroll
    for (int mi = 0; mi < 4; mi++) {
#pragma unroll
        for (int half = 0; half < 2; half++) {
            int i = rowBase + m0 + mi * 16 + g + half * 8;
#pragma unroll
            for (int ni = 0; ni < 8; ni++) {
                float c0 = acc[mi][ni][half * 2 + 0];
                float c1 = acc[mi][ni][half * 2 + 1];
                int col = colBase + n0w + ni * 8 + 2 * tg;
                if (MODE == 0) {
                    if (col < Nout)     Cg[(long)i * Nout + col] = c0;
                    if (col + 1 < Nout) Cg[(long)i * Nout + col + 1] = c1;
                } else if (MODE == 1) {
                    if (i < Me) {
                        float* dst = Cg + (long)e * strideH + (long)i * F_ + col;
                        dst[0] = tf32r(gelu_f(c0));
                        dst[1] = tf32r(gelu_f(c1));
                    }
                } else {
                    if (i < Me) {
                        int t = lists[e * N_ + i];
                        float* dst = Cg + ((long)t * E_ + e) * C_ + col;
                        dst[0] = c0;
                        dst[1] = c1;
                    }
                }
            }
        }
    }
#undef LOADG
}

// ============ fp32 SGEMM 64x64 (attention path, precision-critical) ==================
template <int MODE>  // 0: C = acc; 4: C += acc
__global__ __launch_bounds__(256) void sgemm64(
    const float* __restrict__ A, const float* __restrict__ B, float* __restrict__ Cmat,
    int N, int K)
{
    const int BM = 64, BN = 64, BK = 16;
    __shared__ float As[2][BK][BM + 4];
    __shared__ float Bs[2][BK][BN + 4];

    int tid = threadIdx.x;
    int rowBase = blockIdx.y * BM;
    int colBase = blockIdx.x * BN;
    int tr = tid >> 4, tc = tid & 15;

    float acc[4][4];
#pragma unroll
    for (int i = 0; i < 4; i++)
#pragma unroll
        for (int j = 0; j < 4; j++) acc[i][j] = 0.0f;

    int am = tid & 63;
    int ak = (tid >> 6) * 4;
    const float* Arow = A + (long)(rowBase + am) * K;
    int bk = tid >> 4;
    int bn = (tid & 15) * 4;

    float4 sa, sb;
#define LOADG64(k0)                                                     \
    {                                                                   \
        sa = *(const float4*)(Arow + (k0) + ak);                        \
        sb = *(const float4*)(B + (long)((k0) + bk) * N + colBase + bn);\
    }
#define STS64(bufi)                                                     \
    {                                                                   \
        As[bufi][ak + 0][am] = sa.x;                                    \
        As[bufi][ak + 1][am] = sa.y;                                    \
        As[bufi][ak + 2][am] = sa.z;                                    \
        As[bufi][ak + 3][am] = sa.w;                                    \
        *(float4*)&Bs[bufi][bk][bn] = sb;                               \
    }
    LOADG64(0); STS64(0);
    __syncthreads();
    int buf = 0;
    for (int k0 = 0; k0 < K; k0 += BK) {
        bool has_next = (k0 + BK) < K;
        if (has_next) LOADG64(k0 + BK);
#pragma unroll
        for (int kk = 0; kk < BK; kk++) {
            float4 a4 = *(const float4*)&As[buf][kk][tr * 4];
            float4 b4 = *(const float4*)&Bs[buf][kk][tc * 4];
            float a[4] = {a4.x, a4.y, a4.z, a4.w};
            float b[4] = {b4.x, b4.y, b4.z, b4.w};
#pragma unroll
            for (int i = 0; i < 4; i++)
#pragma unroll
                for (int j = 0; j < 4; j++) acc[i][j] = fmaf(a[i], b[j], acc[i][j]);
        }
        if (has_next) STS64(buf ^ 1);
        __syncthreads();
        buf ^= 1;
    }
#pragma unroll
    for (int i = 0; i < 4; i++) {
        int row = rowBase + tr * 4 + i;
#pragma unroll
        for (int j = 0; j < 4; j++) {
            int col = colBase + tc * 4 + j;
            if (MODE == 0) Cmat[(long)row * N + col] = acc[i][j];
            else           Cmat[(long)row * N + col] += acc[i][j];
        }
    }
#undef LOADG64
#undef STS64
}

// fused QKV: blockIdx.z selects weight/output; N=K=256
__global__ __launch_bounds__(256) void sgemm64_qkv(
    const float* __restrict__ A,
    const float* __restrict__ Wq, const float* __restrict__ Wk, const float* __restrict__ Wv,
    float* __restrict__ Oq, float* __restrict__ Ok, float* __restrict__ Ov)
{
    const int BM = 64, BN = 64, BK = 16, N = 256, K = 256;
    int z = blockIdx.z;
    const float* B = (z == 0) ? Wq : (z == 1) ? Wk : Wv;
    float* Cmat = (z == 0) ? Oq : (z == 1) ? Ok : Ov;

    __shared__ float As[2][BK][BM + 4];
    __shared__ float Bs[2][BK][BN + 4];

    int tid = threadIdx.x;
    int rowBase = blockIdx.y * BM;
    int colBase = blockIdx.x * BN;
    int tr = tid >> 4, tc = tid & 15;

    float acc[4][4];
#pragma unroll
    for (int i = 0; i < 4; i++)
#pragma unroll
        for (int j = 0; j < 4; j++) acc[i][j] = 0.0f;

    int am = tid & 63;
    int ak = (tid >> 6) * 4;
    const float* Arow = A + (long)(rowBase + am) * K;
    int bk = tid >> 4;
    int bn = (tid & 15) * 4;

    float4 sa, sb;
#define LOADG64(k0)                                                     \
    {                                                                   \
        sa = *(const float4*)(Arow + (k0) + ak);                        \
        sb = *(const float4*)(B + (long)((k0) + bk) * N + colBase + bn);\
    }
#define STS64(bufi)                                                     \
    {                                                                   \
        As[bufi][ak + 0][am] = sa.x;                                    \
        As[bufi][ak + 1][am] = sa.y;                                    \
        As[bufi][ak + 2][am] = sa.z;                                    \
        As[bufi][ak + 3][am] = sa.w;                                    \
        *(float4*)&Bs[bufi][bk][bn] = sb;                               \
    }
    LOADG64(0); STS64(0);
    __syncthreads();
    int buf = 0;
    for (int k0 = 0; k0 < K; k0 += BK) {
        bool has_next = (k0 + BK) < K;
        if (has_next) LOADG64(k0 + BK);
#pragma unroll
        for (int kk = 0; kk < BK; kk++) {
            float4 a4 = *(const float4*)&As[buf][kk][tr * 4];
            float4 b4 = *(const float4*)&Bs[buf][kk][tc * 4];
            float a[4] = {a4.x, a4.y, a4.z, a4.w};
            float b[4] = {b4.x, b4.y, b4.z, b4.w};
#pragma unroll
            for (int i = 0; i < 4; i++)
#pragma unroll
                for (int j = 0; j < 4; j++) acc[i][j] = fmaf(a[i], b[j], acc[i][j]);
        }
        if (has_next) STS64(buf ^ 1);
        __syncthreads();
        buf ^= 1;
    }
#pragma unroll
    for (int i = 0; i < 4; i++) {
        int row = rowBase + tr * 4 + i;
#pragma unroll
        for (int j = 0; j < 4; j++)
            Cmat[(long)row * N + colBase + tc * 4 + j] = acc[i][j];
    }
#undef LOADG64
#undef STS64
}

// ---------------- prepass kernels ----------------
__global__ void round4_kernel(const float4* __restrict__ src, float4* __restrict__ dst) {
    size_t i = (size_t)blockIdx.x * blockDim.x + threadIdx.x;
    float4 v = src[i];
    v.x = tf32r(v.x); v.y = tf32r(v.y); v.z = tf32r(v.z); v.w = tf32r(v.w);
    dst[i] = v;
}
// lm_head [C, V] -> padded rounded [C, VP_]
__global__ void round_pad_lmh(const float* __restrict__ src, float* __restrict__ dst) {
    int c = blockIdx.x * 128 + threadIdx.x;
    int r = blockIdx.y;
    dst[(long)r * VP_ + c] = (c < V_) ? tf32r(src[(long)r * V_ + c]) : 0.0f;
}

// ---------------- small kernels ----------------
__global__ void embed_kernel(const int* __restrict__ ids, const float* __restrict__ emb,
                             float* __restrict__ hs) {
    int t = blockIdx.x, c = threadIdx.x;
    hs[t * C_ + c] = emb[(size_t)ids[t] * C_ + c];
}

__global__ void layernorm_k(const float* __restrict__ in, const float* __restrict__ w,
                            const float* __restrict__ b, float* __restrict__ out) {
    int t = blockIdx.x, c = threadIdx.x;
    __shared__ float red[256];
    float x = in[t * C_ + c];
    red[c] = x;
    __syncthreads();
    for (int s = 128; s > 0; s >>= 1) { if (c < s) red[c] += red[c + s]; __syncthreads(); }
    float mu = red[0] * (1.0f / C_);
    __syncthreads();
    float d = x - mu;
    red[c] = d * d;
    __syncthreads();
    for (int s = 128; s > 0; s >>= 1) { if (c < s) red[c] += red[c + s]; __syncthreads(); }
    float var = red[0] * (1.0f / C_);
    out[t * C_ + c] = d * rsqrtf(var + 1e-5f) * w[c] + b[c];
}

__global__ void attn_scores(const float* __restrict__ q, const float* __restrict__ k,
                            float* __restrict__ attn) {
    int bh = blockIdx.z;
    int qt = blockIdx.y * 32, kt = blockIdx.x * 32;
    if (kt > qt + 31) return;
    int b = bh / H_, h = bh % H_;
    int ty = threadIdx.y, tx = threadIdx.x;
    int qi = qt + ty, ki = kt + tx;
    size_t oidx = ((size_t)bh * T_ + qi) * T_ + ki;
    __shared__ float qs[32][33], ks[32][33];
    qs[ty][tx] = q[(size_t)(b * T_ + qt + ty) * C_ + h * D_ + tx];
    ks[ty][tx] = k[(size_t)(b * T_ + kt + ty) * C_ + h * D_ + tx];
    __syncthreads();
    float s;
    if (ki <= qi) {
        float a = 0.0f;
#pragma unroll
        for (int d = 0; d < 32; d++) a = fmaf(qs[ty][d], ks[tx][d], a);
        s = a * 0.17677669529663687f;
    } else {
        s = -1e30f;
    }
    attn[oidx] = s;
}

__global__ void softmax_causal(float* __restrict__ attn) {
    size_t rowg = blockIdx.x;
    int row = (int)(rowg & (T_ - 1));
    int len = row + 1;
    float* p = attn + rowg * (size_t)T_;
    int c = threadIdx.x;
    __shared__ float red[256];
    float v[4];
    float m = -INFINITY;
#pragma unroll
    for (int i = 0; i < 4; i++) {
        int idx = c + 256 * i;
        v[i] = (idx < len) ? p[idx] : -INFINITY;
        m = fmaxf(m, v[i]);
    }
    red[c] = m;
    __syncthreads();
    for (int s = 128; s > 0; s >>= 1) { if (c < s) red[c] = fmaxf(red[c], red[c + s]); __syncthreads(); }
    m = red[0];
    __syncthreads();
    float s = 0.0f;
#pragma unroll
    for (int i = 0; i < 4; i++) { v[i] = expf(v[i] - m); s += v[i]; }
    red[c] = s;
    __syncthreads();
    for (int st = 128; st > 0; st >>= 1) { if (c < st) red[c] += red[c + st]; __syncthreads(); }
    float inv = 1.0f / red[0];
#pragma unroll
    for (int i = 0; i < 4; i++) {
        int idx = c + 256 * i;
        if (idx < len) p[idx] = v[i] * inv;
    }
}

__global__ void attn_av(const float* __restrict__ attn, const float* __restrict__ v,
                        float* __restrict__ ao) {
    int bh = blockIdx.y;
    int b = bh / H_, h = bh % H_;
    int d = threadIdx.x % 32;
    int qi = threadIdx.x / 32;
    int q = blockIdx.x * 8 + qi;
    const float* arow = attn + ((size_t)bh * T_ + q) * T_;
    const float* vbase = v + (size_t)b * T_ * C_ + h * D_ + d;
    float a0 = 0.f, a1 = 0.f, a2 = 0.f, a3 = 0.f;
    int k = 0;
    for (; k + 3 <= q; k += 4) {
        a0 = fmaf(arow[k + 0], vbase[(size_t)(k + 0) * C_], a0);
        a1 = fmaf(arow[k + 1], vbase[(size_t)(k + 1) * C_], a1);
        a2 = fmaf(arow[k + 2], vbase[(size_t)(k + 2) * C_], a2);
        a3 = fmaf(arow[k + 3], vbase[(size_t)(k + 3) * C_], a3);
    }
    for (; k <= q; k++) a0 = fmaf(arow[k], vbase[(size_t)k * C_], a0);
    ao[(size_t)(b * T_ + q) * C_ + h * D_ + d] = (a0 + a1) + (a2 + a3);
}

__global__ void snorm_kernel(const float* __restrict__ sim, float* __restrict__ snorm) {
    int e = blockIdx.x;
    int c = threadIdx.x;
    __shared__ float red[256];
    float v = sim[c * E_ + e];
    red[c] = v * v;
    __syncthreads();
    for (int s = 128; s > 0; s >>= 1) { if (c < s) red[c] += red[c + s]; __syncthreads(); }
    if (c == 0) snorm[e] = sqrtf(red[0]);
}

__global__ void gating_kernel(const float* __restrict__ xt, const float* __restrict__ sim,
                              const float* __restrict__ gates, const float* __restrict__ snorm,
                              float* __restrict__ pre_out, float* __restrict__ amask_out,
                              float* __restrict__ rw) {
    int t = blockIdx.x;
    int lane = threadIdx.x;
    const unsigned FULL = 0xffffffffu;

    float ss = 0.0f;
#pragma unroll
    for (int i = 0; i < 8; i++) { float v = xt[t * C_ + lane + i * 32]; ss += v * v; }
#pragma unroll
    for (int o = 16; o; o >>= 1) ss += __shfl_xor_sync(FULL, ss, o);
    float xnorm = fmaxf(sqrtf(ss), 1e-12f);

    float dot = 0.0f;
    for (int c = 0; c < C_; c++) dot = fmaf(xt[t * C_ + c], sim[c * E_ + lane], dot);
    float logit = dot / (xnorm * fmaxf(snorm[lane], 1e-12f));

    float sig = 1.0f / (1.0f + expf(-gates[lane]));
    float pre = logit - sig;
    pre_out[t * E_ + lane] = pre;

    float gated = fmaxf(pre, 0.0f);
    bool active = pre > 0.0f;
    unsigned bal = __ballot_sync(FULL, active);
    bool sel;
    if (bal == 0u) {
        int rank = 0;
        float my = logit;
#pragma unroll
        for (int j = 0; j < 32; j++) {
            float lj = __shfl_sync(FULL, my, j);
            if (lj > my || (lj == my && j < lane)) rank++;
        }
        sel = rank < (E_ / 2);
    } else {
        sel = active;
    }
    amask_out[t * E_ + lane] = sel ? 1.0f : 0.0f;

    const float NEGV = -3.3895313892515355e38f;
    float gl = sel ? gated : NEGV;
    float m = gl;
#pragma unroll
    for (int o = 16; o; o >>= 1) m = fmaxf(m, __shfl_xor_sync(FULL, m, o));
    float ex = expf(gl - m);
    float s = ex;
#pragma unroll
    for (int o = 16; o; o >>= 1) s += __shfl_xor_sync(FULL, s, o);
    rw[t * E_ + lane] = ex / s;
}

__global__ void build_lists(const float* __restrict__ mask, int* __restrict__ counts,
                            int* __restrict__ lists) {
    int e = blockIdx.x;
    int lane = threadIdx.x;
    int cnt = 0;
    for (int base = 0; base < N_; base += 32) {
        int t = base + lane;
        bool a = mask[t * E_ + e] > 0.5f;
        unsigned bal = __ballot_sync(0xffffffffu, a);
        int pos = cnt + __popc(bal & ((1u << lane) - 1u));
        if (a) lists[e * N_ + pos] = t;
        cnt += __popc(bal);
    }
    if (lane == 0) counts[e] = cnt;
}

__global__ void zero_feo(float4* __restrict__ p) {
    size_t i = (size_t)blockIdx.x * blockDim.x + threadIdx.x;
    p[i] = make_float4(0.f, 0.f, 0.f, 0.f);
}

// skip experts with rw == 0 (softmax of NEG underflows to exactly 0) -> halves feo reads
__global__ void moe_reduce(const float* __restrict__ rw, const float* __restrict__ feo,
                           float* __restrict__ hs) {
    int t = blockIdx.x, c = threadIdx.x;
    __shared__ float srw[E_];
    if (c < E_) srw[c] = rw[t * E_ + c];
    __syncthreads();
    float acc = 0.0f;
#pragma unroll
    for (int e = 0; e < E_; e++) {
        float w = srw[e];
        if (w != 0.0f)
            acc = fmaf(w, feo[((size_t)t * E_ + e) * C_ + c], acc);
    }
    hs[t * C_ + c] += acc;
}

// ---------------- launcher ----------------
extern "C" void kernel_launch(void* const* d_in, const int* in_sizes, int n_in,
                              void* d_out, int out_size) {
    const int*   ids   = (const int*)d_in[0];
    const float* emb   = (const float*)d_in[1];
    const float* wq    = (const float*)d_in[2];
    const float* wk    = (const float*)d_in[3];
    const float* wv    = (const float*)d_in[4];
    const float* wo    = (const float*)d_in[5];
    const float* ln1w  = (const float*)d_in[6];
    const float* ln1b  = (const float*)d_in[7];
    const float* ln2w  = (const float*)d_in[8];
    const float* ln2b  = (const float*)d_in[9];
    const float* sim   = (const float*)d_in[10];
    const float* gates = (const float*)d_in[11];
    const float* w1    = (const float*)d_in[12];
    const float* w2    = (const float*)d_in[13];
    const float* lmh   = (const float*)d_in[14];

    float* out = (float*)d_out;
    float* out_logits = out;
    float* out_feo    = out_logits + (size_t)B_ * T_ * V_;
    float* out_pre    = out_feo + (size_t)N_ * E_ * C_;
    float* out_mask   = out_pre + (size_t)N_ * E_;

    float *hs, *ln, *qb, *kb, *vb, *ao, *attn, *Hbuf, *rw, *snorm;
    float *w1r, *w2r, *lmhr, *lnr, *hsr;
    int *counts, *lists;
    cudaGetSymbolAddress((void**)&hs, g_hs);
    cudaGetSymbolAddress((void**)&ln, g_ln);
    cudaGetSymbolAddress((void**)&qb, g_q);
    cudaGetSymbolAddress((void**)&kb, g_k);
    cudaGetSymbolAddress((void**)&vb, g_v);
    cudaGetSymbolAddress((void**)&ao, g_ao);
    cudaGetSymbolAddress((void**)&attn, g_attn);
    cudaGetSymbolAddress((void**)&Hbuf, g_Hbuf);
    cudaGetSymbolAddress((void**)&rw, g_rw);
    cudaGetSymbolAddress((void**)&snorm, g_snorm);
    cudaGetSymbolAddress((void**)&counts, g_counts);
    cudaGetSymbolAddress((void**)&lists, g_lists);
    cudaGetSymbolAddress((void**)&w1r, g_w1r);
    cudaGetSymbolAddress((void**)&w2r, g_w2r);
    cudaGetSymbolAddress((void**)&lmhr, g_lmhr);
    cudaGetSymbolAddress((void**)&lnr, g_lnr);
    cudaGetSymbolAddress((void**)&hsr, g_hsr);

    // one-time side-stream + events (created outside graph capture on first call)
    static cudaStream_t s2 = nullptr;
    static cudaEvent_t evF = nullptr, evJ = nullptr;
    if (s2 == nullptr) {
        cudaStreamCreateWithFlags(&s2, cudaStreamNonBlocking);
        cudaEventCreateWithFlags(&evF, cudaEventDisableTiming);
        cudaEventCreateWithFlags(&evJ, cudaEventDisableTiming);
    }

    // ---- fork: prepass (independent of residual stream) runs on s2 ----
    cudaEventRecord(evF, 0);
    cudaStreamWaitEvent(s2, evF, 0);
    round4_kernel<<<(E_ * C_ * F_ / 4) / 256, 256, 0, s2>>>((const float4*)w1, (float4*)w1r);
    round4_kernel<<<(E_ * F_ * C_ / 4) / 256, 256, 0, s2>>>((const float4*)w2, (float4*)w2r);
    round_pad_lmh<<<dim3(VP_ / 128, C_), 128, 0, s2>>>(lmh, lmhr);
    zero_feo<<<(N_ * E_ * C_ / 4) / 256, 256, 0, s2>>>((float4*)out_feo);
    cudaEventRecord(evJ, s2);

    // ---- main chain ----
    snorm_kernel<<<E_, 256>>>(sim, snorm);
    embed_kernel<<<N_, 256>>>(ids, emb, hs);
    layernorm_k<<<N_, 256>>>(hs, ln1w, ln1b, ln);

    sgemm64_qkv<<<dim3(C_ / 64, N_ / 64, 3), 256>>>(ln, wq, wk, wv, qb, kb, vb);

    attn_scores<<<dim3(32, 32, B_ * H_), dim3(32, 32)>>>(qb, kb, attn);
    softmax_causal<<<B_ * H_ * T_, 256>>>(attn);
    attn_av<<<dim3(T_ / 8, B_ * H_), 256>>>(attn, vb, ao);

    sgemm64<4><<<dim3(C_ / 64, N_ / 64), 256>>>(ao, wo, hs, C_, C_);   // hs += ao@wo

    layernorm_k<<<N_, 256>>>(hs, ln2w, ln2b, ln);
    round4_kernel<<<(N_ * C_ / 4) / 256, 256>>>((const float4*)ln, (float4*)lnr);
    gating_kernel<<<N_, 32>>>(ln, sim, gates, snorm, out_pre, out_mask, rw);
    build_lists<<<E_, 32>>>(out_mask, counts, lists);

    // ---- join: MoE / LM head need the prepass results ----
    cudaStreamWaitEvent(0, evJ, 0);

    // sparse MoE up: [cnt,256]@[256,1024] per expert, gelu, tf32-rounded compact H
    gemm_tf32p<1><<<dim3(F_ / 128, N_ / 128, E_), 128>>>(
        lnr, w1r, Hbuf, F_, F_, C_, (long)C_ * F_, (long)N_ * F_, lists, counts);
    // sparse MoE down: [cnt,1024]@[1024,256] -> scatter to feo
    gemm_tf32p<2><<<dim3(C_ / 128, N_ / 128, E_), 128>>>(
        Hbuf, w2r, out_feo, C_, C_, F_, (long)F_ * C_, (long)N_ * F_, lists, counts);

    moe_reduce<<<N_, 256>>>(rw, out_feo, hs);
    round4_kernel<<<(N_ * C_ / 4) / 256, 256>>>((const float4*)hs, (float4*)hsr);

    // LM head: [2048,256] @ [256,50304-padded] -> logits[:,:50257]
    gemm_tf32p<0><<<dim3(VP_ / 128, N_ / 128, 1), 128>>>(
        hsr, lmhr, out_logits, VP_, V_, C_, 0, 0, nullptr, nullptr);
}